// round 1
// baseline (speedup 1.0000x reference)
#include <cuda_runtime.h>
#include <cuda_bf16.h>
#include <math.h>

// Problem dims
#define NTOK 1024
#define LL   32
#define DD   768
#define IND  64
#define NOUT 16
#define OUTD 64
#define EPSF 1e-8f

// Scratch (device globals: no cudaMalloc allowed)
__device__ float g_mu[(size_t)LL * NTOK * IND];                 // mu_in [l][n][i]
__device__ float g_f[LL * NTOK];                                // f_a_in [l][n]
__device__ float g_V[(size_t)NTOK * LL * NOUT * OUTD];          // V [n][l][k][o]

__device__ __forceinline__ unsigned long long ffma2(unsigned long long a,
                                                    unsigned long long b,
                                                    unsigned long long c) {
    unsigned long long d;
    asm("fma.rn.f32x2 %0, %1, %2, %3;" : "=l"(d) : "l"(a), "l"(b), "l"(c));
    return d;
}
__device__ __forceinline__ unsigned long long dup2(float x) {
    unsigned int xi = __float_as_uint(x);
    return ((unsigned long long)xi << 32) | (unsigned long long)xi;
}
__device__ __forceinline__ float lo32(unsigned long long v) {
    return __uint_as_float((unsigned int)(v & 0xffffffffu));
}
__device__ __forceinline__ float hi32(unsigned long long v) {
    return __uint_as_float((unsigned int)(v >> 32));
}
__device__ __forceinline__ float wred(float v) {
#pragma unroll
    for (int o = 16; o; o >>= 1) v += __shfl_xor_sync(0xffffffffu, v, o);
    return v;
}

// ---------------------------------------------------------------------------
// K1: per (l, token-tile64): mu_in = gelu(X_l @ Wcap + Bcap),
//     f = sigmoid(X_l @ Wscore + Bscore) * mask
// grid (16, 32), block 256
// ---------------------------------------------------------------------------
__global__ __launch_bounds__(256) void k1_cap(
    const float* __restrict__ x, const float* __restrict__ mask,
    const float* __restrict__ Wscore, const float* __restrict__ Bscore,
    const float* __restrict__ Wcap, const float* __restrict__ Bcap) {
    const int l = blockIdx.y;
    const int n0 = blockIdx.x * 64;
    const int tid = threadIdx.x;
    __shared__ __align__(16) float As[16][68];  // [k][m]
    __shared__ __align__(16) float Bs[16][64];  // [k][o]
    __shared__ float Ws[16];

    unsigned long long acc2[4][2] = {};
    float sacc = 0.0f;
    const int tm = (tid >> 4) << 2, tn = (tid & 15) << 2;
    const float* xl = x + (size_t)n0 * (LL * DD) + (size_t)l * DD;
    const float* wc = Wcap + (size_t)l * DD * IND;
    const float* wsp = Wscore + (size_t)l * DD;
    const int lm = tid >> 2, lv = (tid & 3) << 2;
    const int br = tid >> 4, bv = (tid & 15) << 2;

    for (int kk = 0; kk < DD; kk += 16) {
        float4 xv = *(const float4*)(xl + (size_t)lm * (LL * DD) + kk + lv);
        As[lv + 0][lm] = xv.x; As[lv + 1][lm] = xv.y;
        As[lv + 2][lm] = xv.z; As[lv + 3][lm] = xv.w;
        *(float4*)&Bs[br][bv] = *(const float4*)(wc + (size_t)(kk + br) * IND + bv);
        if (tid < 16) Ws[tid] = wsp[kk + tid];
        __syncthreads();
#pragma unroll
        for (int k = 0; k < 16; k++) {
            float4 a4 = *(const float4*)&As[k][tm];
            ulonglong2 b2 = *(const ulonglong2*)&Bs[k][tn];
            unsigned long long a0 = dup2(a4.x), a1 = dup2(a4.y);
            unsigned long long a2 = dup2(a4.z), a3 = dup2(a4.w);
            acc2[0][0] = ffma2(a0, b2.x, acc2[0][0]); acc2[0][1] = ffma2(a0, b2.y, acc2[0][1]);
            acc2[1][0] = ffma2(a1, b2.x, acc2[1][0]); acc2[1][1] = ffma2(a1, b2.y, acc2[1][1]);
            acc2[2][0] = ffma2(a2, b2.x, acc2[2][0]); acc2[2][1] = ffma2(a2, b2.y, acc2[2][1]);
            acc2[3][0] = ffma2(a3, b2.x, acc2[3][0]); acc2[3][1] = ffma2(a3, b2.y, acc2[3][1]);
            if (tid < 64) sacc = fmaf(As[k][tid], Ws[k], sacc);
        }
        __syncthreads();
    }
#pragma unroll
    for (int i = 0; i < 4; i++) {
        int n = n0 + tm + i;
        float vb[4];
        vb[0] = lo32(acc2[i][0]); vb[1] = hi32(acc2[i][0]);
        vb[2] = lo32(acc2[i][1]); vb[3] = hi32(acc2[i][1]);
        float4 r;
        float* rp = (float*)&r;
#pragma unroll
        for (int j = 0; j < 4; j++) {
            float v = vb[j] + Bcap[l * IND + tn + j];
            rp[j] = 0.5f * v * (1.0f + erff(v * 0.70710678118654752f));
        }
        *(float4*)(g_mu + ((size_t)l * NTOK + n) * IND + tn) = r;
    }
    if (tid < 64) {
        int n = n0 + tid;
        float a = sacc + Bscore[l];
        float s = 1.0f / (1.0f + expf(-a));
        g_f[l * NTOK + n] = s * mask[(size_t)n * LL + l];
    }
}

// ---------------------------------------------------------------------------
// K2: per (token-tile64, k, l): V = mu_in[l] @ Wvote[l,k] + Bvote[l,k]
// V layout [n][l][k][o].  grid (16, 16, 32), block 256
// ---------------------------------------------------------------------------
__global__ __launch_bounds__(256) void k2_vote(
    const float* __restrict__ Wvote, const float* __restrict__ Bvote) {
    const int n0 = blockIdx.x * 64;
    const int kc = blockIdx.y;
    const int l = blockIdx.z;
    const int tid = threadIdx.x;
    __shared__ __align__(16) float As[IND][68];  // [i][m]
    __shared__ __align__(16) float Bs[IND][OUTD];

    {
        const float* mi = g_mu + ((size_t)l * NTOK + n0) * IND;
#pragma unroll
        for (int it = 0; it < 4; it++) {
            int idx = tid + it * 256;
            int m = idx >> 4, v = (idx & 15) << 2;
            float4 t = *(const float4*)(mi + (size_t)m * IND + v);
            As[v + 0][m] = t.x; As[v + 1][m] = t.y;
            As[v + 2][m] = t.z; As[v + 3][m] = t.w;
        }
        const float* wv = Wvote + (size_t)(l * NOUT + kc) * IND * OUTD;
#pragma unroll
        for (int it = 0; it < 4; it++) {
            int idx = tid + it * 256;
            int i = idx >> 4, v = (idx & 15) << 2;
            *(float4*)&Bs[i][v] = *(const float4*)(wv + i * OUTD + v);
        }
    }
    __syncthreads();
    unsigned long long acc2[4][2] = {};
    const int tm = (tid >> 4) << 2, tn = (tid & 15) << 2;
#pragma unroll 8
    for (int i = 0; i < IND; i++) {
        float4 a4 = *(const float4*)&As[i][tm];
        ulonglong2 b2 = *(const ulonglong2*)&Bs[i][tn];
        unsigned long long a0 = dup2(a4.x), a1 = dup2(a4.y);
        unsigned long long a2 = dup2(a4.z), a3 = dup2(a4.w);
        acc2[0][0] = ffma2(a0, b2.x, acc2[0][0]); acc2[0][1] = ffma2(a0, b2.y, acc2[0][1]);
        acc2[1][0] = ffma2(a1, b2.x, acc2[1][0]); acc2[1][1] = ffma2(a1, b2.y, acc2[1][1]);
        acc2[2][0] = ffma2(a2, b2.x, acc2[2][0]); acc2[2][1] = ffma2(a2, b2.y, acc2[2][1]);
        acc2[3][0] = ffma2(a3, b2.x, acc2[3][0]); acc2[3][1] = ffma2(a3, b2.y, acc2[3][1]);
    }
    const float* bvp = Bvote + (size_t)(l * NOUT + kc) * OUTD + tn;
    float b0 = bvp[0], b1 = bvp[1], b2v = bvp[2], b3 = bvp[3];
#pragma unroll
    for (int i = 0; i < 4; i++) {
        int n = n0 + tm + i;
        float4 r;
        r.x = lo32(acc2[i][0]) + b0; r.y = hi32(acc2[i][0]) + b1;
        r.z = lo32(acc2[i][1]) + b2v; r.w = hi32(acc2[i][1]) + b3;
        *(float4*)&g_V[((((size_t)n * LL + l) * NOUT + kc) << 6) + tn] = r;
    }
}

// ---------------------------------------------------------------------------
// K3: routing. One CTA per token, 512 threads, V slice (128 KB) in SMEM.
// ---------------------------------------------------------------------------
#define K3_SMEM_FLOATS (32768 + 1024 * 3 + 512 * 3 + 32 * 2 + 16 * 5 + 16)
__global__ __launch_bounds__(512) void k3_route(
    const float* __restrict__ beta_use, const float* __restrict__ beta_ign,
    const int* __restrict__ iters_p, float* __restrict__ out) {
    extern __shared__ __align__(16) float sm[];
    float* Vs   = sm;              // 32768   [l*16+k][o]
    float* mu   = Vs + 32768;      // 1024    [k][o]
    float* var  = mu + 1024;       // 1024
    float* iv   = var + 1024;      // 1024    1/(2var+eps)
    float* R    = iv + 1024;       // 512     [l][k]
    float* zs   = R + 512;         // 512
    float* ws   = zs + 512;        // 512     w = f*R
    float* fs   = ws + 512;        // 32
    float* bus  = fs + 32;         // 32
    float* bis  = bus + 32;        // 16
    float* lvs  = bis + 16;        // 16
    float* lsa  = lvs + 16;        // 16
    float* aout = lsa + 16;        // 16
    float* sumw = aout + 16;       // 16
    float* sfs  = sumw + 16;       // 1 (+pad)

    const int n = blockIdx.x;
    const int tid = threadIdx.x;
    const int warp = tid >> 5, lane = tid & 31;

    {
        const float4* Vg4 = (const float4*)(g_V + (size_t)n * (LL * NOUT * OUTD));
        float4* Vs4 = (float4*)Vs;
#pragma unroll
        for (int i = 0; i < 16; i++) Vs4[tid + i * 512] = Vg4[tid + i * 512];
    }
    if (tid < 32) { fs[tid] = g_f[tid * NTOK + n]; bus[tid] = beta_use[tid]; }
    if (tid < 16) bis[tid] = beta_ign[tid];
    R[tid] = 1.0f / (float)NOUT;
    __syncthreads();
    if (warp == 0) {
        float v = wred(fs[lane]);
        if (lane == 0) sfs[0] = v;
    }
    __syncthreads();

    const int ITERS = *iters_p;
    for (int t = 0; t < ITERS; t++) {
        if (t > 0) {
            iv[tid]       = 1.0f / (2.0f * var[tid] + EPSF);
            iv[tid + 512] = 1.0f / (2.0f * var[tid + 512] + EPSF);
            {   // lvs[k] = 0.5 * sum_o log(var+eps);  k = warp
                float s = logf(var[(warp << 6) + lane] + EPSF)
                        + logf(var[(warp << 6) + lane + 32] + EPSF);
                s = wred(s);
                if (lane == 0) lvs[warp] = 0.5f * s;
            }
            if (tid < 16) {
                float a = aout[tid];
                lsa[tid] = fminf(a, 0.0f) - log1pf(expf(-fabsf(a)));
            }
            __syncthreads();
            // z[l][k] = lsa[k] - lvs[k] - sum_o (V-mu)^2 * iv   (const terms cancel)
#pragma unroll
            for (int p = 0; p < 32; p++) {
                int pair = (warp << 5) + p;      // pair = l*16 + k
                int k = pair & 15;
                int base = pair << 6;
                int kb = (k << 6) + lane;
                float d1 = Vs[base + lane] - mu[kb];
                float d2 = Vs[base + lane + 32] - mu[kb + 32];
                float s = d1 * d1 * iv[kb] + d2 * d2 * iv[kb + 32];
                s = wred(s);
                if (lane == 0) zs[pair] = lsa[k] - lvs[k] - s;
            }
            __syncthreads();
            if (tid < 32) {  // softmax over k for row l=tid
                int l = tid;
                float m = -1e30f;
#pragma unroll
                for (int k = 0; k < 16; k++) m = fmaxf(m, zs[(l << 4) + k]);
                float e[16], ssum = 0.0f;
#pragma unroll
                for (int k = 0; k < 16; k++) {
                    e[k] = expf(zs[(l << 4) + k] - m);
                    ssum += e[k];
                }
                float invs = 1.0f / ssum;
#pragma unroll
                for (int k = 0; k < 16; k++) R[(l << 4) + k] = e[k] * invs;
            }
            __syncthreads();
        }
        {   // per-k sums; k = warp, l = lane
            int k = warp;
            float w = fs[lane] * R[(lane << 4) + k];
            ws[(lane << 4) + k] = w;
            float wb = bus[lane] * w;
            float wr = wred(w);
            float wbr = wred(wb);
            if (lane == 0) {
                sumw[k] = wr;
                aout[k] = wbr - bis[k] * (sfs[0] - wr);
            }
        }
        __syncthreads();
        {   // mu/var single pass: thread handles (k, o) and (k, o+32)
            int k = tid >> 5, o = tid & 31;
            float S1a = 0, S2a = 0, S1b = 0, S2b = 0;
#pragma unroll
            for (int l = 0; l < 32; l++) {
                float w = ws[(l << 4) + k];
                int base = ((l << 4) + k) << 6;
                float va = Vs[base + o];
                float vb = Vs[base + o + 32];
                float pa = w * va, pb = w * vb;
                S1a += pa; S2a += pa * va;
                S1b += pb; S2b += pb * vb;
            }
            float invd = 1.0f / (sumw[k] + EPSF);
            float mua = S1a * invd, mub = S1b * invd;
            mu[(k << 6) + o] = mua;
            mu[(k << 6) + o + 32] = mub;
            var[(k << 6) + o] = fmaxf(S2a * invd - mua * mua, 0.0f);
            var[(k << 6) + o + 32] = fmaxf(S2b * invd - mub * mub, 0.0f);
        }
        __syncthreads();
    }
    // outputs: a_fin (N,16) then mu_fin (N,16,64)
    if (tid < 16) out[n * NOUT + tid] = aout[tid];
    float* om = out + NTOK * NOUT + (size_t)n * (NOUT * OUTD);
    om[tid] = mu[tid];
    om[tid + 512] = mu[tid + 512];
}

extern "C" void kernel_launch(void* const* d_in, const int* in_sizes, int n_in,
                              void* d_out, int out_size) {
    const float* x        = (const float*)d_in[0];
    const float* mask     = (const float*)d_in[1];
    const float* Wscore   = (const float*)d_in[2];
    const float* Bscore   = (const float*)d_in[3];
    const float* Wcap     = (const float*)d_in[4];
    const float* Bcap     = (const float*)d_in[5];
    const float* Wvote    = (const float*)d_in[6];
    const float* Bvote    = (const float*)d_in[7];
    const float* beta_use = (const float*)d_in[8];
    const float* beta_ign = (const float*)d_in[9];
    const int*   iters    = (const int*)d_in[10];
    float* out = (float*)d_out;

    const size_t smem3 = (size_t)K3_SMEM_FLOATS * sizeof(float);
    cudaFuncSetAttribute(k3_route, cudaFuncAttributeMaxDynamicSharedMemorySize, (int)smem3);

    k1_cap<<<dim3(NTOK / 64, LL), 256>>>(x, mask, Wscore, Bscore, Wcap, Bcap);
    k2_vote<<<dim3(NTOK / 64, NOUT, LL), 256>>>(Wvote, Bvote);
    k3_route<<<NTOK, 512, smem3>>>(beta_use, beta_ign, iters, out);
}

// round 2
// speedup vs baseline: 1.0026x; 1.0026x over previous
#include <cuda_runtime.h>
#include <cuda_bf16.h>
#include <math.h>

// Problem dims
#define NTOK 1024
#define LL   32
#define DD   768
#define IND  64
#define NOUT 16
#define OUTD 64
#define EPSF 1e-8f

// Scratch (device globals: no cudaMalloc allowed)
__device__ float g_mu[(size_t)LL * NTOK * IND];                 // mu_in [l][n][i]
__device__ float g_f[LL * NTOK];                                // f_a_in [l][n]
__device__ float g_V[(size_t)NTOK * LL * NOUT * OUTD];          // V [n][l][k][o]

__device__ __forceinline__ unsigned long long ffma2(unsigned long long a,
                                                    unsigned long long b,
                                                    unsigned long long c) {
    unsigned long long d;
    asm("fma.rn.f32x2 %0, %1, %2, %3;" : "=l"(d) : "l"(a), "l"(b), "l"(c));
    return d;
}
__device__ __forceinline__ unsigned long long dup2(float x) {
    unsigned int xi = __float_as_uint(x);
    return ((unsigned long long)xi << 32) | (unsigned long long)xi;
}
__device__ __forceinline__ float lo32(unsigned long long v) {
    return __uint_as_float((unsigned int)(v & 0xffffffffu));
}
__device__ __forceinline__ float hi32(unsigned long long v) {
    return __uint_as_float((unsigned int)(v >> 32));
}
__device__ __forceinline__ float wred(float v) {
#pragma unroll
    for (int o = 16; o; o >>= 1) v += __shfl_xor_sync(0xffffffffu, v, o);
    return v;
}

// ---------------------------------------------------------------------------
// K1: per (l, token-tile64): mu_in = gelu(X_l @ Wcap + Bcap),
//     f = sigmoid(X_l @ Wscore + Bscore) * mask
// grid (16, 32), block 256
// ---------------------------------------------------------------------------
__global__ __launch_bounds__(256) void k1_cap(
    const float* __restrict__ x, const float* __restrict__ mask,
    const float* __restrict__ Wscore, const float* __restrict__ Bscore,
    const float* __restrict__ Wcap, const float* __restrict__ Bcap) {
    const int l = blockIdx.y;
    const int n0 = blockIdx.x * 64;
    const int tid = threadIdx.x;
    __shared__ __align__(16) float As[16][68];  // [k][m]
    __shared__ __align__(16) float Bs[16][64];  // [k][o]
    __shared__ float Ws[16];

    unsigned long long acc2[4][2] = {};
    float sacc = 0.0f;
    const int tm = (tid >> 4) << 2, tn = (tid & 15) << 2;
    const float* xl = x + (size_t)n0 * (LL * DD) + (size_t)l * DD;
    const float* wc = Wcap + (size_t)l * DD * IND;
    const float* wsp = Wscore + (size_t)l * DD;
    const int lm = tid >> 2, lv = (tid & 3) << 2;
    const int br = tid >> 4, bv = (tid & 15) << 2;

    for (int kk = 0; kk < DD; kk += 16) {
        float4 xv = *(const float4*)(xl + (size_t)lm * (LL * DD) + kk + lv);
        As[lv + 0][lm] = xv.x; As[lv + 1][lm] = xv.y;
        As[lv + 2][lm] = xv.z; As[lv + 3][lm] = xv.w;
        *(float4*)&Bs[br][bv] = *(const float4*)(wc + (size_t)(kk + br) * IND + bv);
        if (tid < 16) Ws[tid] = wsp[kk + tid];
        __syncthreads();
#pragma unroll
        for (int k = 0; k < 16; k++) {
            float4 a4 = *(const float4*)&As[k][tm];
            ulonglong2 b2 = *(const ulonglong2*)&Bs[k][tn];
            unsigned long long a0 = dup2(a4.x), a1 = dup2(a4.y);
            unsigned long long a2 = dup2(a4.z), a3 = dup2(a4.w);
            acc2[0][0] = ffma2(a0, b2.x, acc2[0][0]); acc2[0][1] = ffma2(a0, b2.y, acc2[0][1]);
            acc2[1][0] = ffma2(a1, b2.x, acc2[1][0]); acc2[1][1] = ffma2(a1, b2.y, acc2[1][1]);
            acc2[2][0] = ffma2(a2, b2.x, acc2[2][0]); acc2[2][1] = ffma2(a2, b2.y, acc2[2][1]);
            acc2[3][0] = ffma2(a3, b2.x, acc2[3][0]); acc2[3][1] = ffma2(a3, b2.y, acc2[3][1]);
            if (tid < 64) sacc = fmaf(As[k][tid], Ws[k], sacc);
        }
        __syncthreads();
    }
#pragma unroll
    for (int i = 0; i < 4; i++) {
        int n = n0 + tm + i;
        float vb[4];
        vb[0] = lo32(acc2[i][0]); vb[1] = hi32(acc2[i][0]);
        vb[2] = lo32(acc2[i][1]); vb[3] = hi32(acc2[i][1]);
        float4 r;
        float* rp = (float*)&r;
#pragma unroll
        for (int j = 0; j < 4; j++) {
            float v = vb[j] + Bcap[l * IND + tn + j];
            rp[j] = 0.5f * v * (1.0f + erff(v * 0.70710678118654752f));
        }
        *(float4*)(g_mu + ((size_t)l * NTOK + n) * IND + tn) = r;
    }
    if (tid < 64) {
        int n = n0 + tid;
        float a = sacc + Bscore[l];
        float s = 1.0f / (1.0f + expf(-a));
        g_f[l * NTOK + n] = s * mask[(size_t)n * LL + l];
    }
}

// ---------------------------------------------------------------------------
// K2: per (token-tile64, k, l): V = mu_in[l] @ Wvote[l,k] + Bvote[l,k]
// V layout [n][l][k][o].  grid (16, 16, 32), block 256
// ---------------------------------------------------------------------------
__global__ __launch_bounds__(256) void k2_vote(
    const float* __restrict__ Wvote, const float* __restrict__ Bvote) {
    const int n0 = blockIdx.x * 64;
    const int kc = blockIdx.y;
    const int l = blockIdx.z;
    const int tid = threadIdx.x;
    __shared__ __align__(16) float As[IND][68];  // [i][m]
    __shared__ __align__(16) float Bs[IND][OUTD];

    {
        const float* mi = g_mu + ((size_t)l * NTOK + n0) * IND;
#pragma unroll
        for (int it = 0; it < 4; it++) {
            int idx = tid + it * 256;
            int m = idx >> 4, v = (idx & 15) << 2;
            float4 t = *(const float4*)(mi + (size_t)m * IND + v);
            As[v + 0][m] = t.x; As[v + 1][m] = t.y;
            As[v + 2][m] = t.z; As[v + 3][m] = t.w;
        }
        const float* wv = Wvote + (size_t)(l * NOUT + kc) * IND * OUTD;
#pragma unroll
        for (int it = 0; it < 4; it++) {
            int idx = tid + it * 256;
            int i = idx >> 4, v = (idx & 15) << 2;
            *(float4*)&Bs[i][v] = *(const float4*)(wv + i * OUTD + v);
        }
    }
    __syncthreads();
    unsigned long long acc2[4][2] = {};
    const int tm = (tid >> 4) << 2, tn = (tid & 15) << 2;
#pragma unroll 8
    for (int i = 0; i < IND; i++) {
        float4 a4 = *(const float4*)&As[i][tm];
        ulonglong2 b2 = *(const ulonglong2*)&Bs[i][tn];
        unsigned long long a0 = dup2(a4.x), a1 = dup2(a4.y);
        unsigned long long a2 = dup2(a4.z), a3 = dup2(a4.w);
        acc2[0][0] = ffma2(a0, b2.x, acc2[0][0]); acc2[0][1] = ffma2(a0, b2.y, acc2[0][1]);
        acc2[1][0] = ffma2(a1, b2.x, acc2[1][0]); acc2[1][1] = ffma2(a1, b2.y, acc2[1][1]);
        acc2[2][0] = ffma2(a2, b2.x, acc2[2][0]); acc2[2][1] = ffma2(a2, b2.y, acc2[2][1]);
        acc2[3][0] = ffma2(a3, b2.x, acc2[3][0]); acc2[3][1] = ffma2(a3, b2.y, acc2[3][1]);
    }
    const float* bvp = Bvote + (size_t)(l * NOUT + kc) * OUTD + tn;
    float b0 = bvp[0], b1 = bvp[1], b2v = bvp[2], b3 = bvp[3];
#pragma unroll
    for (int i = 0; i < 4; i++) {
        int n = n0 + tm + i;
        float4 r;
        r.x = lo32(acc2[i][0]) + b0; r.y = hi32(acc2[i][0]) + b1;
        r.z = lo32(acc2[i][1]) + b2v; r.w = hi32(acc2[i][1]) + b3;
        *(float4*)&g_V[((((size_t)n * LL + l) * NOUT + kc) << 6) + tn] = r;
    }
}

// ---------------------------------------------------------------------------
// K3: routing. One CTA per token, 512 threads, V slice (128 KB) in SMEM.
// ---------------------------------------------------------------------------
#define K3_SMEM_FLOATS (32768 + 1024 * 3 + 512 * 3 + 32 * 2 + 16 * 5 + 16)
__global__ __launch_bounds__(512) void k3_route(
    const float* __restrict__ beta_use, const float* __restrict__ beta_ign,
    const int* __restrict__ iters_p, float* __restrict__ out) {
    extern __shared__ __align__(16) float sm[];
    float* Vs   = sm;              // 32768   [l*16+k][o]
    float* mu   = Vs + 32768;      // 1024    [k][o]
    float* var  = mu + 1024;       // 1024
    float* iv   = var + 1024;      // 1024    1/(2var+eps)
    float* R    = iv + 1024;       // 512     [l][k]
    float* zs   = R + 512;         // 512
    float* ws   = zs + 512;        // 512     w = f*R
    float* fs   = ws + 512;        // 32
    float* bus  = fs + 32;         // 32
    float* bis  = bus + 32;        // 16
    float* lvs  = bis + 16;        // 16
    float* lsa  = lvs + 16;        // 16
    float* aout = lsa + 16;        // 16
    float* sumw = aout + 16;       // 16
    float* sfs  = sumw + 16;       // 1 (+pad)

    const int n = blockIdx.x;
    const int tid = threadIdx.x;
    const int warp = tid >> 5, lane = tid & 31;

    {
        const float4* Vg4 = (const float4*)(g_V + (size_t)n * (LL * NOUT * OUTD));
        float4* Vs4 = (float4*)Vs;
#pragma unroll
        for (int i = 0; i < 16; i++) Vs4[tid + i * 512] = Vg4[tid + i * 512];
    }
    if (tid < 32) { fs[tid] = g_f[tid * NTOK + n]; bus[tid] = beta_use[tid]; }
    if (tid < 16) bis[tid] = beta_ign[tid];
    R[tid] = 1.0f / (float)NOUT;
    __syncthreads();
    if (warp == 0) {
        float v = wred(fs[lane]);
        if (lane == 0) sfs[0] = v;
    }
    __syncthreads();

    const int ITERS = *iters_p;
    for (int t = 0; t < ITERS; t++) {
        if (t > 0) {
            iv[tid]       = 1.0f / (2.0f * var[tid] + EPSF);
            iv[tid + 512] = 1.0f / (2.0f * var[tid + 512] + EPSF);
            {   // lvs[k] = 0.5 * sum_o log(var+eps);  k = warp
                float s = logf(var[(warp << 6) + lane] + EPSF)
                        + logf(var[(warp << 6) + lane + 32] + EPSF);
                s = wred(s);
                if (lane == 0) lvs[warp] = 0.5f * s;
            }
            if (tid < 16) {
                float a = aout[tid];
                lsa[tid] = fminf(a, 0.0f) - log1pf(expf(-fabsf(a)));
            }
            __syncthreads();
            // z[l][k] = lsa[k] - lvs[k] - sum_o (V-mu)^2 * iv   (const terms cancel)
#pragma unroll
            for (int p = 0; p < 32; p++) {
                int pair = (warp << 5) + p;      // pair = l*16 + k
                int k = pair & 15;
                int base = pair << 6;
                int kb = (k << 6) + lane;
                float d1 = Vs[base + lane] - mu[kb];
                float d2 = Vs[base + lane + 32] - mu[kb + 32];
                float s = d1 * d1 * iv[kb] + d2 * d2 * iv[kb + 32];
                s = wred(s);
                if (lane == 0) zs[pair] = lsa[k] - lvs[k] - s;
            }
            __syncthreads();
            if (tid < 32) {  // softmax over k for row l=tid
                int l = tid;
                float m = -1e30f;
#pragma unroll
                for (int k = 0; k < 16; k++) m = fmaxf(m, zs[(l << 4) + k]);
                float e[16], ssum = 0.0f;
#pragma unroll
                for (int k = 0; k < 16; k++) {
                    e[k] = expf(zs[(l << 4) + k] - m);
                    ssum += e[k];
                }
                float invs = 1.0f / ssum;
#pragma unroll
                for (int k = 0; k < 16; k++) R[(l << 4) + k] = e[k] * invs;
            }
            __syncthreads();
        }
        {   // per-k sums; k = warp, l = lane
            int k = warp;
            float w = fs[lane] * R[(lane << 4) + k];
            ws[(lane << 4) + k] = w;
            float wb = bus[lane] * w;
            float wr = wred(w);
            float wbr = wred(wb);
            if (lane == 0) {
                sumw[k] = wr;
                aout[k] = wbr - bis[k] * (sfs[0] - wr);
            }
        }
        __syncthreads();
        {   // mu/var single pass: thread handles (k, o) and (k, o+32)
            int k = tid >> 5, o = tid & 31;
            float S1a = 0, S2a = 0, S1b = 0, S2b = 0;
#pragma unroll
            for (int l = 0; l < 32; l++) {
                float w = ws[(l << 4) + k];
                int base = ((l << 4) + k) << 6;
                float va = Vs[base + o];
                float vb = Vs[base + o + 32];
                float pa = w * va, pb = w * vb;
                S1a += pa; S2a += pa * va;
                S1b += pb; S2b += pb * vb;
            }
            float invd = 1.0f / (sumw[k] + EPSF);
            float mua = S1a * invd, mub = S1b * invd;
            mu[(k << 6) + o] = mua;
            mu[(k << 6) + o + 32] = mub;
            var[(k << 6) + o] = fmaxf(S2a * invd - mua * mua, 0.0f);
            var[(k << 6) + o + 32] = fmaxf(S2b * invd - mub * mub, 0.0f);
        }
        __syncthreads();
    }
    // outputs: a_fin (N,16) then mu_fin (N,16,64)
    if (tid < 16) out[n * NOUT + tid] = aout[tid];
    float* om = out + NTOK * NOUT + (size_t)n * (NOUT * OUTD);
    om[tid] = mu[tid];
    om[tid + 512] = mu[tid + 512];
}

extern "C" void kernel_launch(void* const* d_in, const int* in_sizes, int n_in,
                              void* d_out, int out_size) {
    const float* x        = (const float*)d_in[0];
    const float* mask     = (const float*)d_in[1];
    const float* Wscore   = (const float*)d_in[2];
    const float* Bscore   = (const float*)d_in[3];
    const float* Wcap     = (const float*)d_in[4];
    const float* Bcap     = (const float*)d_in[5];
    const float* Wvote    = (const float*)d_in[6];
    const float* Bvote    = (const float*)d_in[7];
    const float* beta_use = (const float*)d_in[8];
    const float* beta_ign = (const float*)d_in[9];
    const int*   iters    = (const int*)d_in[10];
    float* out = (float*)d_out;

    const size_t smem3 = (size_t)K3_SMEM_FLOATS * sizeof(float);
    cudaFuncSetAttribute(k3_route, cudaFuncAttributeMaxDynamicSharedMemorySize, (int)smem3);

    k1_cap<<<dim3(NTOK / 64, LL), 256>>>(x, mask, Wscore, Bscore, Wcap, Bcap);
    k2_vote<<<dim3(NTOK / 64, NOUT, LL), 256>>>(Wvote, Bvote);
    k3_route<<<NTOK, 512, smem3>>>(beta_use, beta_ign, iters, out);
}

// round 6
// speedup vs baseline: 1.2554x; 1.2521x over previous
#include <cuda_runtime.h>
#include <math.h>
#include <stdint.h>

#define NTOK 1024
#define LL   32
#define DD   768
#define IND  64
#define NOUT 16
#define OUTD 64
#define EPSF 1e-8f

__device__ float g_mu[(size_t)LL * NTOK * IND];        // [l][n][i]
__device__ float g_f[LL * NTOK];                       // [l][n]
__device__ float g_V[(size_t)NTOK * LL * NOUT * OUTD]; // [n][l][k][o]

__device__ __forceinline__ float tf32r(float x) {
    uint32_t o;
    asm("cvt.rn.tf32.f32 %0, %1;" : "=r"(o) : "f"(x));
    return __uint_as_float(o);
}
__device__ __forceinline__ void mma8(float c[4], uint32_t a0, uint32_t a1,
                                     uint32_t a2, uint32_t a3,
                                     uint32_t b0, uint32_t b1) {
    asm("mma.sync.aligned.m16n8k8.row.col.f32.tf32.tf32.f32 "
        "{%0,%1,%2,%3}, {%4,%5,%6,%7}, {%8,%9}, {%0,%1,%2,%3};"
        : "+f"(c[0]), "+f"(c[1]), "+f"(c[2]), "+f"(c[3])
        : "r"(a0), "r"(a1), "r"(a2), "r"(a3), "r"(b0), "r"(b1));
}
__device__ __forceinline__ float gelu(float v) {
    return 0.5f * v * (1.0f + erff(v * 0.70710678118654752f));
}
__device__ __forceinline__ float wred(float v) {
#pragma unroll
    for (int o = 16; o; o >>= 1) v += __shfl_xor_sync(0xffffffffu, v, o);
    return v;
}

// ---------------------------------------------------------------------------
// K1 (mma.sync 2xTF32-compensated): per (l, 256-token tile):
//   mu_in = gelu(X_l @ Wcap + Bcap), f = sigmoid(X_l @ Wscore + Bscore)*mask
// grid (4, 32), block 256 (8 warps). 48 K-chunks of 16.
// Warp: M=32 (2 m16 frags), N=64 (8 n8 tiles). 3 MMA passes (hh, lh, hl).
// ---------------------------------------------------------------------------
#define AS1 20   // As row stride (16 + 4 pad)
#define BS1 72   // Bs row stride (64 + 8 pad)
#define K1_DYN ((2 * 256 * AS1 + 2 * 16 * BS1 + 16 + 64) * 4)
__global__ __launch_bounds__(256) void k1h(
    const float* __restrict__ x, const float* __restrict__ mask,
    const float* __restrict__ Wscore, const float* __restrict__ Bscore,
    const float* __restrict__ Wcap, const float* __restrict__ Bcap) {
    extern __shared__ __align__(16) float s1[];
    float* Ah = s1;                      // [256][AS1]
    float* Al = Ah + 256 * AS1;
    float* Bh = Al + 256 * AS1;          // [16][BS1]
    float* Bl = Bh + 16 * BS1;
    float* Ws = Bl + 16 * BS1;           // [16]
    float* bcs = Ws + 16;                // [64]

    const int l = blockIdx.y, n0 = blockIdx.x * 256;
    const int tid = threadIdx.x, wid = tid >> 5, lane = tid & 31;
    const int g = lane >> 2, tig = lane & 3;

    if (tid < 64) bcs[tid] = Bcap[l * IND + tid];

    const float* xl = x + (size_t)(n0 + tid) * (LL * DD) + (size_t)l * DD;
    const float* wc = Wcap + (size_t)l * DD * IND;
    const int bi = tid & 63, bk = (tid >> 6) << 2;

    // prefetch chunk 0
    float4 a_st[4];
    float b_st[4];
    float w_st = 0.0f;
#pragma unroll
    for (int j = 0; j < 4; j++) a_st[j] = *(const float4*)(xl + j * 4);
#pragma unroll
    for (int j = 0; j < 4; j++) b_st[j] = wc[(size_t)(bk + j) * IND + bi];
    if (tid < 16) w_st = Wscore[l * DD + tid];

    float acc[2][8][4] = {};
    float sacc = 0.0f;

    for (int c = 0; c < 48; c++) {
        __syncthreads();
#pragma unroll
        for (int j = 0; j < 4; j++) {
            float4 h, lo;
            h.x = tf32r(a_st[j].x); lo.x = tf32r(a_st[j].x - h.x);
            h.y = tf32r(a_st[j].y); lo.y = tf32r(a_st[j].y - h.y);
            h.z = tf32r(a_st[j].z); lo.z = tf32r(a_st[j].z - h.z);
            h.w = tf32r(a_st[j].w); lo.w = tf32r(a_st[j].w - h.w);
            *(float4*)(Ah + tid * AS1 + j * 4) = h;
            *(float4*)(Al + tid * AS1 + j * 4) = lo;
        }
#pragma unroll
        for (int j = 0; j < 4; j++) {
            float h = tf32r(b_st[j]);
            Bh[(bk + j) * BS1 + bi] = h;
            Bl[(bk + j) * BS1 + bi] = tf32r(b_st[j] - h);
        }
        if (tid < 16) Ws[tid] = w_st;
        __syncthreads();

        // score partial (full fp32, thread t owns token n0+t)
#pragma unroll
        for (int j = 0; j < 4; j++) {
            sacc += a_st[j].x * Ws[j * 4 + 0] + a_st[j].y * Ws[j * 4 + 1]
                  + a_st[j].z * Ws[j * 4 + 2] + a_st[j].w * Ws[j * 4 + 3];
        }
        // prefetch next chunk
        if (c + 1 < 48) {
            int k0 = (c + 1) * 16;
#pragma unroll
            for (int j = 0; j < 4; j++) a_st[j] = *(const float4*)(xl + k0 + j * 4);
#pragma unroll
            for (int j = 0; j < 4; j++) b_st[j] = wc[(size_t)(k0 + bk + j) * IND + bi];
            if (tid < 16) w_st = Wscore[l * DD + k0 + tid];
        }
        // mma over the chunk (2 k8 steps, 3 compensated passes)
#pragma unroll
        for (int ks = 0; ks < 2; ks++) {
            const int kk = ks * 8;
            uint32_t ah[2][4], al[2][4];
#pragma unroll
            for (int mf = 0; mf < 2; mf++) {
                int r = wid * 32 + mf * 16;
                ah[mf][0] = __float_as_uint(Ah[(r + g) * AS1 + kk + tig]);
                ah[mf][1] = __float_as_uint(Ah[(r + g + 8) * AS1 + kk + tig]);
                ah[mf][2] = __float_as_uint(Ah[(r + g) * AS1 + kk + tig + 4]);
                ah[mf][3] = __float_as_uint(Ah[(r + g + 8) * AS1 + kk + tig + 4]);
                al[mf][0] = __float_as_uint(Al[(r + g) * AS1 + kk + tig]);
                al[mf][1] = __float_as_uint(Al[(r + g + 8) * AS1 + kk + tig]);
                al[mf][2] = __float_as_uint(Al[(r + g) * AS1 + kk + tig + 4]);
                al[mf][3] = __float_as_uint(Al[(r + g + 8) * AS1 + kk + tig + 4]);
            }
#pragma unroll
            for (int nt = 0; nt < 8; nt++) {
                uint32_t bh0 = __float_as_uint(Bh[(kk + tig) * BS1 + nt * 8 + g]);
                uint32_t bh1 = __float_as_uint(Bh[(kk + tig + 4) * BS1 + nt * 8 + g]);
                uint32_t bl0 = __float_as_uint(Bl[(kk + tig) * BS1 + nt * 8 + g]);
                uint32_t bl1 = __float_as_uint(Bl[(kk + tig + 4) * BS1 + nt * 8 + g]);
#pragma unroll
                for (int mf = 0; mf < 2; mf++) {
                    mma8(acc[mf][nt], al[mf][0], al[mf][1], al[mf][2], al[mf][3], bh0, bh1);
                    mma8(acc[mf][nt], ah[mf][0], ah[mf][1], ah[mf][2], ah[mf][3], bl0, bl1);
                    mma8(acc[mf][nt], ah[mf][0], ah[mf][1], ah[mf][2], ah[mf][3], bh0, bh1);
                }
            }
        }
    }
    // epilogue: bias + GELU -> g_mu
#pragma unroll
    for (int mf = 0; mf < 2; mf++) {
        int r0 = wid * 32 + mf * 16 + g;
#pragma unroll
        for (int nt = 0; nt < 8; nt++) {
            int col = nt * 8 + 2 * tig;
            float b0v = bcs[col], b1v = bcs[col + 1];
            float2 v0, v1;
            v0.x = gelu(acc[mf][nt][0] + b0v);
            v0.y = gelu(acc[mf][nt][1] + b1v);
            v1.x = gelu(acc[mf][nt][2] + b0v);
            v1.y = gelu(acc[mf][nt][3] + b1v);
            *(float2*)(g_mu + ((size_t)l * NTOK + n0 + r0) * IND + col) = v0;
            *(float2*)(g_mu + ((size_t)l * NTOK + n0 + r0 + 8) * IND + col) = v1;
        }
    }
    {
        int n = n0 + tid;
        float a = sacc + Bscore[l];
        float s = 1.0f / (1.0f + expf(-a));
        g_f[l * NTOK + n] = s * mask[(size_t)n * LL + l];
    }
}

// ---------------------------------------------------------------------------
// K2 (mma.sync 2xTF32-compensated): per (128-token tile, capsule pair, l):
//   V[n,l,k,o] = mu_in[l] @ Wvote[l,k] + Bvote.  M=128, N=128, K=64.
// grid (8, 8, 32), block 256. Warp: M=32, N=64 (one capsule).
// ---------------------------------------------------------------------------
#define AS2 68    // A row stride (64 + 4)
#define BS2 136   // B row stride (128 + 8)
#define K2_DYN ((2 * 128 * AS2 + 2 * 64 * BS2 + 128) * 4)
__global__ __launch_bounds__(256) void k2h(const float* __restrict__ Wvote,
                                           const float* __restrict__ Bvote) {
    extern __shared__ __align__(16) float s2[];
    float* Ah = s2;                      // [128][AS2]
    float* Al = Ah + 128 * AS2;
    float* Bh = Al + 128 * AS2;          // [64][BS2] (row=i, col=kl*64+o)
    float* Bl = Bh + 64 * BS2;
    float* bias = Bl + 64 * BS2;         // [128]

    const int n0 = blockIdx.x * 128, kg = blockIdx.y, l = blockIdx.z;
    const int tid = threadIdx.x, wid = tid >> 5, lane = tid & 31;
    const int g = lane >> 2, tig = lane & 3;

    {
        int m = tid & 127, half = tid >> 7;
        const float* mp = g_mu + ((size_t)l * NTOK + n0 + m) * IND + half * 32;
#pragma unroll
        for (int j = 0; j < 8; j++) {
            float4 v = *(const float4*)(mp + j * 4);
            float4 h, lo;
            h.x = tf32r(v.x); lo.x = tf32r(v.x - h.x);
            h.y = tf32r(v.y); lo.y = tf32r(v.y - h.y);
            h.z = tf32r(v.z); lo.z = tf32r(v.z - h.z);
            h.w = tf32r(v.w); lo.w = tf32r(v.w - h.w);
            *(float4*)(Ah + m * AS2 + half * 32 + j * 4) = h;
            *(float4*)(Al + m * AS2 + half * 32 + j * 4) = lo;
        }
    }
    {
        int o = tid & 63, kl = (tid >> 6) & 1, ih = tid >> 7;
        const float* wv = Wvote + ((size_t)(l * NOUT + kg * 2 + kl) * IND) * OUTD + o;
#pragma unroll
        for (int j = 0; j < 32; j++) {
            int i = ih * 32 + j;
            float v = wv[(size_t)i * OUTD];
            float h = tf32r(v);
            Bh[i * BS2 + kl * 64 + o] = h;
            Bl[i * BS2 + kl * 64 + o] = tf32r(v - h);
        }
    }
    if (tid < 128)
        bias[tid] = Bvote[(size_t)(l * NOUT + kg * 2 + (tid >> 6)) * OUTD + (tid & 63)];
    __syncthreads();

    const int mrow0 = (wid & 3) * 32, nhalf = wid >> 2;
    float acc[2][8][4] = {};
#pragma unroll
    for (int ks = 0; ks < 8; ks++) {
        const int kk = ks * 8;
        uint32_t ah[2][4], al[2][4];
#pragma unroll
        for (int mf = 0; mf < 2; mf++) {
            int r = mrow0 + mf * 16;
            ah[mf][0] = __float_as_uint(Ah[(r + g) * AS2 + kk + tig]);
            ah[mf][1] = __float_as_uint(Ah[(r + g + 8) * AS2 + kk + tig]);
            ah[mf][2] = __float_as_uint(Ah[(r + g) * AS2 + kk + tig + 4]);
            ah[mf][3] = __float_as_uint(Ah[(r + g + 8) * AS2 + kk + tig + 4]);
            al[mf][0] = __float_as_uint(Al[(r + g) * AS2 + kk + tig]);
            al[mf][1] = __float_as_uint(Al[(r + g + 8) * AS2 + kk + tig]);
            al[mf][2] = __float_as_uint(Al[(r + g) * AS2 + kk + tig + 4]);
            al[mf][3] = __float_as_uint(Al[(r + g + 8) * AS2 + kk + tig + 4]);
        }
#pragma unroll
        for (int nt = 0; nt < 8; nt++) {
            int n = nhalf * 64 + nt * 8 + g;
            uint32_t bh0 = __float_as_uint(Bh[(kk + tig) * BS2 + n]);
            uint32_t bh1 = __float_as_uint(Bh[(kk + tig + 4) * BS2 + n]);
            uint32_t bl0 = __float_as_uint(Bl[(kk + tig) * BS2 + n]);
            uint32_t bl1 = __float_as_uint(Bl[(kk + tig + 4) * BS2 + n]);
#pragma unroll
            for (int mf = 0; mf < 2; mf++) {
                mma8(acc[mf][nt], al[mf][0], al[mf][1], al[mf][2], al[mf][3], bh0, bh1);
                mma8(acc[mf][nt], ah[mf][0], ah[mf][1], ah[mf][2], ah[mf][3], bl0, bl1);
                mma8(acc[mf][nt], ah[mf][0], ah[mf][1], ah[mf][2], ah[mf][3], bh0, bh1);
            }
        }
    }
    const int kc = kg * 2 + nhalf;
#pragma unroll
    for (int mf = 0; mf < 2; mf++) {
        int r0 = mrow0 + mf * 16 + g;
#pragma unroll
        for (int nt = 0; nt < 8; nt++) {
            int col = nt * 8 + 2 * tig;
            float b0v = bias[nhalf * 64 + col], b1v = bias[nhalf * 64 + col + 1];
            float2 v0, v1;
            v0.x = acc[mf][nt][0] + b0v; v0.y = acc[mf][nt][1] + b1v;
            v1.x = acc[mf][nt][2] + b0v; v1.y = acc[mf][nt][3] + b1v;
            *(float2*)(g_V + (((size_t)(n0 + r0) * LL + l) * NOUT + kc) * OUTD + col) = v0;
            *(float2*)(g_V + (((size_t)(n0 + r0 + 8) * LL + l) * NOUT + kc) * OUTD + col) = v1;
        }
    }
}

// ---------------------------------------------------------------------------
// K3: routing. One CTA per token, 512 threads, V slice (128 KB) in SMEM.
// ---------------------------------------------------------------------------
#define K3_SMEM_FLOATS (32768 + 1024 * 3 + 512 * 3 + 32 * 2 + 16 * 5 + 16)
__global__ __launch_bounds__(512) void k3_route(
    const float* __restrict__ beta_use, const float* __restrict__ beta_ign,
    const int* __restrict__ iters_p, float* __restrict__ out) {
    extern __shared__ __align__(16) float sm[];
    float* Vs   = sm;
    float* mu   = Vs + 32768;
    float* var  = mu + 1024;
    float* iv   = var + 1024;
    float* R    = iv + 1024;
    float* zs   = R + 512;
    float* ws   = zs + 512;
    float* fs   = ws + 512;
    float* bus  = fs + 32;
    float* bis  = bus + 32;
    float* lvs  = bis + 16;
    float* lsa  = lvs + 16;
    float* aout = lsa + 16;
    float* sumw = aout + 16;
    float* sfs  = sumw + 16;

    const int n = blockIdx.x;
    const int tid = threadIdx.x;
    const int warp = tid >> 5, lane = tid & 31;

    {
        const float4* Vg4 = (const float4*)(g_V + (size_t)n * (LL * NOUT * OUTD));
        float4* Vs4 = (float4*)Vs;
#pragma unroll
        for (int i = 0; i < 16; i++) Vs4[tid + i * 512] = Vg4[tid + i * 512];
    }
    if (tid < 32) { fs[tid] = g_f[tid * NTOK + n]; bus[tid] = beta_use[tid]; }
    if (tid < 16) bis[tid] = beta_ign[tid];
    R[tid] = 1.0f / (float)NOUT;
    __syncthreads();
    if (warp == 0) {
        float v = wred(fs[lane]);
        if (lane == 0) sfs[0] = v;
    }
    __syncthreads();

    const int ITERS = *iters_p;
    for (int t = 0; t < ITERS; t++) {
        if (t > 0) {
            iv[tid]       = 1.0f / (2.0f * var[tid] + EPSF);
            iv[tid + 512] = 1.0f / (2.0f * var[tid + 512] + EPSF);
            {
                float s = logf(var[(warp << 6) + lane] + EPSF)
                        + logf(var[(warp << 6) + lane + 32] + EPSF);
                s = wred(s);
                if (lane == 0) lvs[warp] = 0.5f * s;
            }
            if (tid < 16) {
                float a = aout[tid];
                lsa[tid] = fminf(a, 0.0f) - log1pf(expf(-fabsf(a)));
            }
            __syncthreads();
#pragma unroll
            for (int p = 0; p < 32; p++) {
                int pair = (warp << 5) + p;
                int k = pair & 15;
                int base = pair << 6;
                int kb = (k << 6) + lane;
                float d1 = Vs[base + lane] - mu[kb];
                float d2 = Vs[base + lane + 32] - mu[kb + 32];
                float s = d1 * d1 * iv[kb] + d2 * d2 * iv[kb + 32];
                s = wred(s);
                if (lane == 0) zs[pair] = lsa[k] - lvs[k] - s;
            }
            __syncthreads();
            if (tid < 32) {
                int l = tid;
                float m = -1e30f;
#pragma unroll
                for (int k = 0; k < 16; k++) m = fmaxf(m, zs[(l << 4) + k]);
                float e[16], ssum = 0.0f;
#pragma unroll
                for (int k = 0; k < 16; k++) {
                    e[k] = expf(zs[(l << 4) + k] - m);
                    ssum += e[k];
                }
                float invs = 1.0f / ssum;
#pragma unroll
                for (int k = 0; k < 16; k++) R[(l << 4) + k] = e[k] * invs;
            }
            __syncthreads();
        }
        {
            int k = warp;
            float w = fs[lane] * R[(lane << 4) + k];
            ws[(lane << 4) + k] = w;
            float wb = bus[lane] * w;
            float wr = wred(w);
            float wbr = wred(wb);
            if (lane == 0) {
                sumw[k] = wr;
                aout[k] = wbr - bis[k] * (sfs[0] - wr);
            }
        }
        __syncthreads();
        {
            int k = tid >> 5, o = tid & 31;
            float S1a = 0, S2a = 0, S1b = 0, S2b = 0;
#pragma unroll
            for (int l = 0; l < 32; l++) {
                float w = ws[(l << 4) + k];
                int base = ((l << 4) + k) << 6;
                float va = Vs[base + o];
                float vb = Vs[base + o + 32];
                float pa = w * va, pb = w * vb;
                S1a += pa; S2a += pa * va;
                S1b += pb; S2b += pb * vb;
            }
            float invd = 1.0f / (sumw[k] + EPSF);
            float mua = S1a * invd, mub = S1b * invd;
            mu[(k << 6) + o] = mua;
            mu[(k << 6) + o + 32] = mub;
            var[(k << 6) + o] = fmaxf(S2a * invd - mua * mua, 0.0f);
            var[(k << 6) + o + 32] = fmaxf(S2b * invd - mub * mub, 0.0f);
        }
        __syncthreads();
    }
    if (tid < 16) out[n * NOUT + tid] = aout[tid];
    float* om = out + NTOK * NOUT + (size_t)n * (NOUT * OUTD);
    om[tid] = mu[tid];
    om[tid + 512] = mu[tid + 512];
}

extern "C" void kernel_launch(void* const* d_in, const int* in_sizes, int n_in,
                              void* d_out, int out_size) {
    const float* x        = (const float*)d_in[0];
    const float* mask     = (const float*)d_in[1];
    const float* Wscore   = (const float*)d_in[2];
    const float* Bscore   = (const float*)d_in[3];
    const float* Wcap     = (const float*)d_in[4];
    const float* Bcap     = (const float*)d_in[5];
    const float* Wvote    = (const float*)d_in[6];
    const float* Bvote    = (const float*)d_in[7];
    const float* beta_use = (const float*)d_in[8];
    const float* beta_ign = (const float*)d_in[9];
    const int*   iters    = (const int*)d_in[10];
    float* out = (float*)d_out;

    const size_t smem3 = (size_t)K3_SMEM_FLOATS * sizeof(float);
    cudaFuncSetAttribute(k1h, cudaFuncAttributeMaxDynamicSharedMemorySize, K1_DYN);
    cudaFuncSetAttribute(k2h, cudaFuncAttributeMaxDynamicSharedMemorySize, K2_DYN);
    cudaFuncSetAttribute(k3_route, cudaFuncAttributeMaxDynamicSharedMemorySize, (int)smem3);

    k1h<<<dim3(NTOK / 256, LL), 256, K1_DYN>>>(x, mask, Wscore, Bscore, Wcap, Bcap);
    k2h<<<dim3(NTOK / 128, NOUT / 2, LL), 256, K2_DYN>>>(Wvote, Bvote);
    k3_route<<<NTOK, 512, smem3>>>(beta_use, beta_ign, iters, out);
}

// round 7
// speedup vs baseline: 1.4262x; 1.1360x over previous
#include <cuda_runtime.h>
#include <math.h>
#include <stdint.h>

#define NTOK 1024
#define LL   32
#define DD   768
#define IND  64
#define NOUT 16
#define OUTD 64
#define EPSF 1e-8f

__device__ float g_mu[(size_t)LL * NTOK * IND];        // [l][n][i]
__device__ float g_f[LL * NTOK];                       // [l][n]
__device__ float g_V[(size_t)NTOK * LL * NOUT * OUTD]; // [n][l][k][o]

__device__ __forceinline__ float tf32r(float x) {
    uint32_t o;
    asm("cvt.rn.tf32.f32 %0, %1;" : "=r"(o) : "f"(x));
    return __uint_as_float(o);
}
__device__ __forceinline__ void mma8(float c[4], uint32_t a0, uint32_t a1,
                                     uint32_t a2, uint32_t a3,
                                     uint32_t b0, uint32_t b1) {
    asm("mma.sync.aligned.m16n8k8.row.col.f32.tf32.tf32.f32 "
        "{%0,%1,%2,%3}, {%4,%5,%6,%7}, {%8,%9}, {%0,%1,%2,%3};"
        : "+f"(c[0]), "+f"(c[1]), "+f"(c[2]), "+f"(c[3])
        : "r"(a0), "r"(a1), "r"(a2), "r"(a3), "r"(b0), "r"(b1));
}
__device__ __forceinline__ float gelu(float v) {
    return 0.5f * v * (1.0f + erff(v * 0.70710678118654752f));
}
__device__ __forceinline__ float wred(float v) {
#pragma unroll
    for (int o = 16; o; o >>= 1) v += __shfl_xor_sync(0xffffffffu, v, o);
    return v;
}

// ---------------------------------------------------------------------------
// K1 (mma.sync 2xTF32, fp32-in-SMEM): per (l, 128-token tile):
//   mu_in = gelu(X_l @ Wcap + Bcap), f = sigmoid(X_l @ Wscore + Bscore)*mask
// grid (8, 32) = 256 CTAs, block 128 (4 warps). 48 K-chunks of 16.
// Warp: M=32 (2 m16 frags), N=64 (8 n8 tiles). hi/lo split at frag load.
// ---------------------------------------------------------------------------
#define AS1 20   // As row stride (16 + 4 pad)
#define BS1 72   // Bs row stride (64 + 8 pad)
__global__ __launch_bounds__(128) void k1h(
    const float* __restrict__ x, const float* __restrict__ mask,
    const float* __restrict__ Wscore, const float* __restrict__ Bscore,
    const float* __restrict__ Wcap, const float* __restrict__ Bcap) {
    __shared__ __align__(16) float As[128 * AS1];
    __shared__ __align__(16) float Bs[16 * BS1];
    __shared__ float Ws[16];
    __shared__ float bcs[64];

    const int l = blockIdx.y, n0 = blockIdx.x * 128;
    const int tid = threadIdx.x, wid = tid >> 5, lane = tid & 31;
    const int g = lane >> 2, tig = lane & 3;

    if (tid < 64) bcs[tid] = Bcap[l * IND + tid];

    const float* xl = x + (size_t)(n0 + tid) * (LL * DD) + (size_t)l * DD;
    const float* wc = Wcap + (size_t)l * DD * IND;
    const int bi = tid & 63, bk8 = (tid >> 6) * 8;

    // prefetch chunk 0
    float4 a_st[4];
    float b_st[8];
    float w_st = 0.0f;
#pragma unroll
    for (int j = 0; j < 4; j++) a_st[j] = *(const float4*)(xl + j * 4);
#pragma unroll
    for (int j = 0; j < 8; j++) b_st[j] = wc[(size_t)(bk8 + j) * IND + bi];
    if (tid < 16) w_st = Wscore[l * DD + tid];

    float acc[2][8][4] = {};
    float sacc = 0.0f;

    for (int c = 0; c < 48; c++) {
        __syncthreads();
#pragma unroll
        for (int j = 0; j < 4; j++) *(float4*)(As + tid * AS1 + j * 4) = a_st[j];
#pragma unroll
        for (int j = 0; j < 8; j++) Bs[(bk8 + j) * BS1 + bi] = b_st[j];
        if (tid < 16) Ws[tid] = w_st;
        __syncthreads();

        // score partial (full fp32; thread t owns token n0+t)
#pragma unroll
        for (int j = 0; j < 4; j++) {
            sacc += a_st[j].x * Ws[j * 4 + 0] + a_st[j].y * Ws[j * 4 + 1]
                  + a_st[j].z * Ws[j * 4 + 2] + a_st[j].w * Ws[j * 4 + 3];
        }
        // prefetch next chunk (overlaps mma)
        if (c + 1 < 48) {
            int k0 = (c + 1) * 16;
#pragma unroll
            for (int j = 0; j < 4; j++) a_st[j] = *(const float4*)(xl + k0 + j * 4);
#pragma unroll
            for (int j = 0; j < 8; j++) b_st[j] = wc[(size_t)(k0 + bk8 + j) * IND + bi];
            if (tid < 16) w_st = Wscore[l * DD + k0 + tid];
        }
        // mma over the chunk (2 k8 steps, 3 compensated passes)
#pragma unroll
        for (int ks = 0; ks < 2; ks++) {
            const int kk = ks * 8;
            uint32_t ah[2][4], al[2][4];
#pragma unroll
            for (int mf = 0; mf < 2; mf++) {
                int r = wid * 32 + mf * 16;
                float v0 = As[(r + g) * AS1 + kk + tig];
                float v1 = As[(r + g + 8) * AS1 + kk + tig];
                float v2 = As[(r + g) * AS1 + kk + tig + 4];
                float v3 = As[(r + g + 8) * AS1 + kk + tig + 4];
                float h0 = tf32r(v0), h1 = tf32r(v1), h2 = tf32r(v2), h3 = tf32r(v3);
                ah[mf][0] = __float_as_uint(h0); al[mf][0] = __float_as_uint(tf32r(v0 - h0));
                ah[mf][1] = __float_as_uint(h1); al[mf][1] = __float_as_uint(tf32r(v1 - h1));
                ah[mf][2] = __float_as_uint(h2); al[mf][2] = __float_as_uint(tf32r(v2 - h2));
                ah[mf][3] = __float_as_uint(h3); al[mf][3] = __float_as_uint(tf32r(v3 - h3));
            }
#pragma unroll
            for (int nt = 0; nt < 8; nt++) {
                float bv0 = Bs[(kk + tig) * BS1 + nt * 8 + g];
                float bv1 = Bs[(kk + tig + 4) * BS1 + nt * 8 + g];
                float bh0f = tf32r(bv0), bh1f = tf32r(bv1);
                uint32_t bh0 = __float_as_uint(bh0f), bh1 = __float_as_uint(bh1f);
                uint32_t bl0 = __float_as_uint(tf32r(bv0 - bh0f));
                uint32_t bl1 = __float_as_uint(tf32r(bv1 - bh1f));
#pragma unroll
                for (int mf = 0; mf < 2; mf++) {
                    mma8(acc[mf][nt], al[mf][0], al[mf][1], al[mf][2], al[mf][3], bh0, bh1);
                    mma8(acc[mf][nt], ah[mf][0], ah[mf][1], ah[mf][2], ah[mf][3], bl0, bl1);
                    mma8(acc[mf][nt], ah[mf][0], ah[mf][1], ah[mf][2], ah[mf][3], bh0, bh1);
                }
            }
        }
    }
    // epilogue: bias + GELU -> g_mu
#pragma unroll
    for (int mf = 0; mf < 2; mf++) {
        int r0 = wid * 32 + mf * 16 + g;
#pragma unroll
        for (int nt = 0; nt < 8; nt++) {
            int col = nt * 8 + 2 * tig;
            float b0v = bcs[col], b1v = bcs[col + 1];
            float2 v0, v1;
            v0.x = gelu(acc[mf][nt][0] + b0v);
            v0.y = gelu(acc[mf][nt][1] + b1v);
            v1.x = gelu(acc[mf][nt][2] + b0v);
            v1.y = gelu(acc[mf][nt][3] + b1v);
            *(float2*)(g_mu + ((size_t)l * NTOK + n0 + r0) * IND + col) = v0;
            *(float2*)(g_mu + ((size_t)l * NTOK + n0 + r0 + 8) * IND + col) = v1;
        }
    }
    {
        int n = n0 + tid;
        float a = sacc + Bscore[l];
        float s = 1.0f / (1.0f + expf(-a));
        g_f[l * NTOK + n] = s * mask[(size_t)n * LL + l];
    }
}

// ---------------------------------------------------------------------------
// K2 (mma.sync 2xTF32, fp32-in-SMEM): per (128-token tile, capsule pair, l):
//   V[n,l,k,o] = mu_in[l] @ Wvote[l,k] + Bvote.  M=128, N=128, K=64.
// grid (8, 8, 32), block 256. Warp: M=32, N=64 (one capsule). ~70 KB SMEM.
// ---------------------------------------------------------------------------
#define AS2 68    // A row stride (64 + 4)
#define BS2 136   // B row stride (128 + 8)
#define K2_DYN ((128 * AS2 + 64 * BS2 + 128) * 4)
__global__ __launch_bounds__(256) void k2h(const float* __restrict__ Wvote,
                                           const float* __restrict__ Bvote) {
    extern __shared__ __align__(16) float s2[];
    float* As = s2;                      // [128][AS2] fp32
    float* Bs = As + 128 * AS2;          // [64][BS2]  (row=i, col=kl*64+o) fp32
    float* bias = Bs + 64 * BS2;         // [128]

    const int n0 = blockIdx.x * 128, kg = blockIdx.y, l = blockIdx.z;
    const int tid = threadIdx.x, wid = tid >> 5, lane = tid & 31;
    const int g = lane >> 2, tig = lane & 3;

    {
        int m = tid & 127, half = tid >> 7;
        const float* mp = g_mu + ((size_t)l * NTOK + n0 + m) * IND + half * 32;
#pragma unroll
        for (int j = 0; j < 8; j++)
            *(float4*)(As + m * AS2 + half * 32 + j * 4) = *(const float4*)(mp + j * 4);
    }
    {
        int o = tid & 63, kl = (tid >> 6) & 1, ih = tid >> 7;
        const float* wv = Wvote + ((size_t)(l * NOUT + kg * 2 + kl) * IND) * OUTD + o;
#pragma unroll
        for (int j = 0; j < 32; j++) {
            int i = ih * 32 + j;
            Bs[i * BS2 + kl * 64 + o] = wv[(size_t)i * OUTD];
        }
    }
    if (tid < 128)
        bias[tid] = Bvote[(size_t)(l * NOUT + kg * 2 + (tid >> 6)) * OUTD + (tid & 63)];
    __syncthreads();

    const int mrow0 = (wid & 3) * 32, nhalf = wid >> 2;
    float acc[2][8][4] = {};
#pragma unroll
    for (int ks = 0; ks < 8; ks++) {
        const int kk = ks * 8;
        uint32_t ah[2][4], al[2][4];
#pragma unroll
        for (int mf = 0; mf < 2; mf++) {
            int r = mrow0 + mf * 16;
            float v0 = As[(r + g) * AS2 + kk + tig];
            float v1 = As[(r + g + 8) * AS2 + kk + tig];
            float v2 = As[(r + g) * AS2 + kk + tig + 4];
            float v3 = As[(r + g + 8) * AS2 + kk + tig + 4];
            float h0 = tf32r(v0), h1 = tf32r(v1), h2 = tf32r(v2), h3 = tf32r(v3);
            ah[mf][0] = __float_as_uint(h0); al[mf][0] = __float_as_uint(tf32r(v0 - h0));
            ah[mf][1] = __float_as_uint(h1); al[mf][1] = __float_as_uint(tf32r(v1 - h1));
            ah[mf][2] = __float_as_uint(h2); al[mf][2] = __float_as_uint(tf32r(v2 - h2));
            ah[mf][3] = __float_as_uint(h3); al[mf][3] = __float_as_uint(tf32r(v3 - h3));
        }
#pragma unroll
        for (int nt = 0; nt < 8; nt++) {
            int n = nhalf * 64 + nt * 8 + g;
            float bv0 = Bs[(kk + tig) * BS2 + n];
            float bv1 = Bs[(kk + tig + 4) * BS2 + n];
            float bh0f = tf32r(bv0), bh1f = tf32r(bv1);
            uint32_t bh0 = __float_as_uint(bh0f), bh1 = __float_as_uint(bh1f);
            uint32_t bl0 = __float_as_uint(tf32r(bv0 - bh0f));
            uint32_t bl1 = __float_as_uint(tf32r(bv1 - bh1f));
#pragma unroll
            for (int mf = 0; mf < 2; mf++) {
                mma8(acc[mf][nt], al[mf][0], al[mf][1], al[mf][2], al[mf][3], bh0, bh1);
                mma8(acc[mf][nt], ah[mf][0], ah[mf][1], ah[mf][2], ah[mf][3], bl0, bl1);
                mma8(acc[mf][nt], ah[mf][0], ah[mf][1], ah[mf][2], ah[mf][3], bh0, bh1);
            }
        }
    }
    const int kc = kg * 2 + nhalf;
#pragma unroll
    for (int mf = 0; mf < 2; mf++) {
        int r0 = mrow0 + mf * 16 + g;
#pragma unroll
        for (int nt = 0; nt < 8; nt++) {
            int col = nt * 8 + 2 * tig;
            float b0v = bias[nhalf * 64 + col], b1v = bias[nhalf * 64 + col + 1];
            float2 v0, v1;
            v0.x = acc[mf][nt][0] + b0v; v0.y = acc[mf][nt][1] + b1v;
            v1.x = acc[mf][nt][2] + b0v; v1.y = acc[mf][nt][3] + b1v;
            *(float2*)(g_V + (((size_t)(n0 + r0) * LL + l) * NOUT + kc) * OUTD + col) = v0;
            *(float2*)(g_V + (((size_t)(n0 + r0 + 8) * LL + l) * NOUT + kc) * OUTD + col) = v1;
        }
    }
}

// ---------------------------------------------------------------------------
// K3: routing. One CTA per token, 512 threads (16 warps), V in SMEM.
// Vectorized LDS: z-pass float2 warp-per-k, mu/var pass float4 l-split.
// ---------------------------------------------------------------------------
#define K3_SMEM_FLOATS (32768 + 1024 * 3 + 512 * 3 + 32 * 2 + 16 * 5 + 16)
__global__ __launch_bounds__(512) void k3_route(
    const float* __restrict__ beta_use, const float* __restrict__ beta_ign,
    const int* __restrict__ iters_p, float* __restrict__ out) {
    extern __shared__ __align__(16) float sm[];
    float* Vs   = sm;              // [512 pairs][64]
    float* mu   = Vs + 32768;      // [16][64]
    float* var  = mu + 1024;
    float* iv   = var + 1024;
    float* R    = iv + 1024;       // [32][16]
    float* zs   = R + 512;
    float* ws   = zs + 512;
    float* fs   = ws + 512;
    float* bus  = fs + 32;
    float* bis  = bus + 32;
    float* lvs  = bis + 16;
    float* lsa  = lvs + 16;
    float* aout = lsa + 16;
    float* sumw = aout + 16;
    float* sfs  = sumw + 16;

    const int n = blockIdx.x;
    const int tid = threadIdx.x;
    const int warp = tid >> 5, lane = tid & 31;

    {
        const float4* Vg4 = (const float4*)(g_V + (size_t)n * (LL * NOUT * OUTD));
        float4* Vs4 = (float4*)Vs;
#pragma unroll
        for (int i = 0; i < 16; i++) Vs4[tid + i * 512] = Vg4[tid + i * 512];
    }
    if (tid < 32) { fs[tid] = g_f[tid * NTOK + n]; bus[tid] = beta_use[tid]; }
    if (tid < 16) bis[tid] = beta_ign[tid];
    R[tid] = 1.0f / (float)NOUT;
    __syncthreads();
    if (warp == 0) {
        float v = wred(fs[lane]);
        if (lane == 0) sfs[0] = v;
    }
    __syncthreads();

    const int ITERS = *iters_p;
    for (int t = 0; t < ITERS; t++) {
        if (t > 0) {
            iv[tid]       = 1.0f / (2.0f * var[tid] + EPSF);
            iv[tid + 512] = 1.0f / (2.0f * var[tid + 512] + EPSF);
            {
                float s = logf(var[(warp << 6) + lane] + EPSF)
                        + logf(var[(warp << 6) + lane + 32] + EPSF);
                s = wred(s);
                if (lane == 0) lvs[warp] = 0.5f * s;
            }
            if (tid < 16) {
                float a = aout[tid];
                lsa[tid] = fminf(a, 0.0f) - log1pf(expf(-fabsf(a)));
            }
            __syncthreads();
            // z-pass: warp w handles k=w over all 32 l's; mu/iv cached in regs
            {
                const int k = warp;
                float2 mu2 = *(float2*)&mu[(k << 6) + 2 * lane];
                float2 iv2 = *(float2*)&iv[(k << 6) + 2 * lane];
                float basek = lsa[k] - lvs[k];
#pragma unroll
                for (int li = 0; li < 32; li++) {
                    int pair = (li << 4) + k;
                    float2 v = *(float2*)&Vs[(pair << 6) + 2 * lane];
                    float d0 = v.x - mu2.x, d1 = v.y - mu2.y;
                    float s = d0 * d0 * iv2.x + d1 * d1 * iv2.y;
                    s = wred(s);
                    if (lane == 0) zs[pair] = basek - s;
                }
            }
            __syncthreads();
            if (tid < 32) {
                int l = tid;
                float m = -1e30f;
#pragma unroll
                for (int k = 0; k < 16; k++) m = fmaxf(m, zs[(l << 4) + k]);
                float e[16], ssum = 0.0f;
#pragma unroll
                for (int k = 0; k < 16; k++) {
                    e[k] = expf(zs[(l << 4) + k] - m);
                    ssum += e[k];
                }
                float invs = 1.0f / ssum;
#pragma unroll
                for (int k = 0; k < 16; k++) R[(l << 4) + k] = e[k] * invs;
            }
            __syncthreads();
        }
        {
            int k = warp;
            float w = fs[lane] * R[(lane << 4) + k];
            ws[(lane << 4) + k] = w;
            float wb = bus[lane] * w;
            float wr = wred(w);
            float wbr = wred(wb);
            if (lane == 0) {
                sumw[k] = wr;
                aout[k] = wbr - bis[k] * (sfs[0] - wr);
            }
        }
        __syncthreads();
        // mu/var: warp w -> k=w; half-warps split l; float4 over o
        {
            const int k = warp;
            const int lh = lane >> 4;       // l half (0: l<16, 1: l>=16)
            const int q = lane & 15;        // o quad (o = 4q)
            float4 S1 = {0.f, 0.f, 0.f, 0.f}, S2 = {0.f, 0.f, 0.f, 0.f};
#pragma unroll
            for (int li = 0; li < 16; li++) {
                int lidx = lh * 16 + li;
                float w = ws[(lidx << 4) + k];
                float4 v = *(const float4*)&Vs[(((lidx << 4) + k) << 6) + 4 * q];
                S1.x += w * v.x; S2.x += w * v.x * v.x;
                S1.y += w * v.y; S2.y += w * v.y * v.y;
                S1.z += w * v.z; S2.z += w * v.z * v.z;
                S1.w += w * v.w; S2.w += w * v.w * v.w;
            }
            S1.x += __shfl_xor_sync(0xffffffffu, S1.x, 16);
            S1.y += __shfl_xor_sync(0xffffffffu, S1.y, 16);
            S1.z += __shfl_xor_sync(0xffffffffu, S1.z, 16);
            S1.w += __shfl_xor_sync(0xffffffffu, S1.w, 16);
            S2.x += __shfl_xor_sync(0xffffffffu, S2.x, 16);
            S2.y += __shfl_xor_sync(0xffffffffu, S2.y, 16);
            S2.z += __shfl_xor_sync(0xffffffffu, S2.z, 16);
            S2.w += __shfl_xor_sync(0xffffffffu, S2.w, 16);
            if (lh == 0) {
                float invd = 1.0f / (sumw[k] + EPSF);
                float4 m4, v4;
                m4.x = S1.x * invd; m4.y = S1.y * invd;
                m4.z = S1.z * invd; m4.w = S1.w * invd;
                v4.x = fmaxf(S2.x * invd - m4.x * m4.x, 0.0f);
                v4.y = fmaxf(S2.y * invd - m4.y * m4.y, 0.0f);
                v4.z = fmaxf(S2.z * invd - m4.z * m4.z, 0.0f);
                v4.w = fmaxf(S2.w * invd - m4.w * m4.w, 0.0f);
                *(float4*)&mu[(k << 6) + 4 * q] = m4;
                *(float4*)&var[(k << 6) + 4 * q] = v4;
            }
        }
        __syncthreads();
    }
    if (tid < 16) out[n * NOUT + tid] = aout[tid];
    float* om = out + NTOK * NOUT + (size_t)n * (NOUT * OUTD);
    om[tid] = mu[tid];
    om[tid + 512] = mu[tid + 512];
}

extern "C" void kernel_launch(void* const* d_in, const int* in_sizes, int n_in,
                              void* d_out, int out_size) {
    const float* x        = (const float*)d_in[0];
    const float* mask     = (const float*)d_in[1];
    const float* Wscore   = (const float*)d_in[2];
    const float* Bscore   = (const float*)d_in[3];
    const float* Wcap     = (const float*)d_in[4];
    const float* Bcap     = (const float*)d_in[5];
    const float* Wvote    = (const float*)d_in[6];
    const float* Bvote    = (const float*)d_in[7];
    const float* beta_use = (const float*)d_in[8];
    const float* beta_ign = (const float*)d_in[9];
    const int*   iters    = (const int*)d_in[10];
    float* out = (float*)d_out;

    const size_t smem3 = (size_t)K3_SMEM_FLOATS * sizeof(float);
    cudaFuncSetAttribute(k2h, cudaFuncAttributeMaxDynamicSharedMemorySize, K2_DYN);
    cudaFuncSetAttribute(k3_route, cudaFuncAttributeMaxDynamicSharedMemorySize, (int)smem3);

    k1h<<<dim3(NTOK / 128, LL), 128>>>(x, mask, Wscore, Bscore, Wcap, Bcap);
    k2h<<<dim3(NTOK / 128, NOUT / 2, LL), 256, K2_DYN>>>(Wvote, Bvote);
    k3_route<<<NTOK, 512, smem3>>>(beta_use, beta_ign, iters, out);
}

// round 8
// speedup vs baseline: 1.5025x; 1.0535x over previous
#include <cuda_runtime.h>
#include <math.h>
#include <stdint.h>

#define NTOK 1024
#define LL   32
#define DD   768
#define IND  64
#define NOUT 16
#define OUTD 64
#define EPSF 1e-8f

__device__ float g_mu[(size_t)LL * NTOK * IND];        // [l][n][i]
__device__ float g_f[LL * NTOK];                       // [l][n]
__device__ float g_V[(size_t)NTOK * LL * NOUT * OUTD]; // [n][l][k][o]

__device__ __forceinline__ float tf32r(float x) {
    uint32_t o;
    asm("cvt.rn.tf32.f32 %0, %1;" : "=r"(o) : "f"(x));
    return __uint_as_float(o);
}
__device__ __forceinline__ void mma8(float c[4], uint32_t a0, uint32_t a1,
                                     uint32_t a2, uint32_t a3,
                                     uint32_t b0, uint32_t b1) {
    asm("mma.sync.aligned.m16n8k8.row.col.f32.tf32.tf32.f32 "
        "{%0,%1,%2,%3}, {%4,%5,%6,%7}, {%8,%9}, {%0,%1,%2,%3};"
        : "+f"(c[0]), "+f"(c[1]), "+f"(c[2]), "+f"(c[3])
        : "r"(a0), "r"(a1), "r"(a2), "r"(a3), "r"(b0), "r"(b1));
}
__device__ __forceinline__ float gelu(float v) {
    return 0.5f * v * (1.0f + erff(v * 0.70710678118654752f));
}
__device__ __forceinline__ float wred(float v) {
#pragma unroll
    for (int o = 16; o; o >>= 1) v += __shfl_xor_sync(0xffffffffu, v, o);
    return v;
}

// ---------------------------------------------------------------------------
// K1 (mma.sync 2xTF32): per (l, 128-token tile). Block 256 (8 warps),
// warp = M16 x N64 tile. 48 K-chunks of 16.
// ---------------------------------------------------------------------------
#define AS1 20   // As row stride (16 + 4 pad)
#define BS1 72   // Bs row stride (64 + 8 pad)
__global__ __launch_bounds__(256) void k1h(
    const float* __restrict__ x, const float* __restrict__ mask,
    const float* __restrict__ Wscore, const float* __restrict__ Bscore,
    const float* __restrict__ Wcap, const float* __restrict__ Bcap) {
    __shared__ __align__(16) float As[128 * AS1];
    __shared__ __align__(16) float Bs[16 * BS1];
    __shared__ float Ws[16];
    __shared__ float bcs[64];
    __shared__ float sred[256];

    const int l = blockIdx.y, n0 = blockIdx.x * 128;
    const int tid = threadIdx.x, wid = tid >> 5, lane = tid & 31;
    const int g = lane >> 2, tig = lane & 3;
    const int arow = tid & 127, ahalf = tid >> 7;      // A staging: row, k-half
    const int brow = tid >> 4, bcol4 = (tid & 15) * 4; // B staging

    if (tid < 64) bcs[tid] = Bcap[l * IND + tid];

    const float* xl = x + (size_t)(n0 + arow) * (LL * DD) + (size_t)l * DD + ahalf * 8;
    const float* wc = Wcap + (size_t)l * DD * IND;

    // prefetch chunk 0
    float4 a_st[2];
    float4 b_st;
    float w_st = 0.0f;
    a_st[0] = *(const float4*)(xl);
    a_st[1] = *(const float4*)(xl + 4);
    b_st = *(const float4*)(wc + (size_t)brow * IND + bcol4);
    if (tid < 16) w_st = Wscore[l * DD + tid];

    float acc[8][4] = {};
    float sacc = 0.0f;

    for (int c = 0; c < 48; c++) {
        __syncthreads();
        *(float4*)(As + arow * AS1 + ahalf * 8) = a_st[0];
        *(float4*)(As + arow * AS1 + ahalf * 8 + 4) = a_st[1];
        Bs[brow * BS1 + bcol4 + 0] = b_st.x;
        Bs[brow * BS1 + bcol4 + 1] = b_st.y;
        Bs[brow * BS1 + bcol4 + 2] = b_st.z;
        Bs[brow * BS1 + bcol4 + 3] = b_st.w;
        if (tid < 16) Ws[tid] = w_st;
        __syncthreads();

        // score partial (full fp32; thread covers its staged 8 k's)
        {
            int kb = ahalf * 8;
            sacc += a_st[0].x * Ws[kb + 0] + a_st[0].y * Ws[kb + 1]
                  + a_st[0].z * Ws[kb + 2] + a_st[0].w * Ws[kb + 3]
                  + a_st[1].x * Ws[kb + 4] + a_st[1].y * Ws[kb + 5]
                  + a_st[1].z * Ws[kb + 6] + a_st[1].w * Ws[kb + 7];
        }
        // prefetch next chunk (overlaps mma)
        if (c + 1 < 48) {
            int k0 = (c + 1) * 16;
            a_st[0] = *(const float4*)(xl + k0);
            a_st[1] = *(const float4*)(xl + k0 + 4);
            b_st = *(const float4*)(wc + (size_t)(k0 + brow) * IND + bcol4);
            if (tid < 16) w_st = Wscore[l * DD + k0 + tid];
        }
        // mma: 2 k8 steps, 3 compensated passes, warp tile M16
#pragma unroll
        for (int ks = 0; ks < 2; ks++) {
            const int kk = ks * 8;
            uint32_t ah[4], al[4];
            {
                int r = wid * 16;
                float v0 = As[(r + g) * AS1 + kk + tig];
                float v1 = As[(r + g + 8) * AS1 + kk + tig];
                float v2 = As[(r + g) * AS1 + kk + tig + 4];
                float v3 = As[(r + g + 8) * AS1 + kk + tig + 4];
                float h0 = tf32r(v0), h1 = tf32r(v1), h2 = tf32r(v2), h3 = tf32r(v3);
                ah[0] = __float_as_uint(h0); al[0] = __float_as_uint(tf32r(v0 - h0));
                ah[1] = __float_as_uint(h1); al[1] = __float_as_uint(tf32r(v1 - h1));
                ah[2] = __float_as_uint(h2); al[2] = __float_as_uint(tf32r(v2 - h2));
                ah[3] = __float_as_uint(h3); al[3] = __float_as_uint(tf32r(v3 - h3));
            }
#pragma unroll
            for (int nt = 0; nt < 8; nt++) {
                float bv0 = Bs[(kk + tig) * BS1 + nt * 8 + g];
                float bv1 = Bs[(kk + tig + 4) * BS1 + nt * 8 + g];
                float bh0f = tf32r(bv0), bh1f = tf32r(bv1);
                uint32_t bh0 = __float_as_uint(bh0f), bh1 = __float_as_uint(bh1f);
                uint32_t bl0 = __float_as_uint(tf32r(bv0 - bh0f));
                uint32_t bl1 = __float_as_uint(tf32r(bv1 - bh1f));
                mma8(acc[nt], al[0], al[1], al[2], al[3], bh0, bh1);
                mma8(acc[nt], ah[0], ah[1], ah[2], ah[3], bl0, bl1);
                mma8(acc[nt], ah[0], ah[1], ah[2], ah[3], bh0, bh1);
            }
        }
    }
    // epilogue: bias + GELU -> g_mu  (warp rows wid*16+g, +8)
    {
        int r0 = wid * 16 + g;
#pragma unroll
        for (int nt = 0; nt < 8; nt++) {
            int col = nt * 8 + 2 * tig;
            float b0v = bcs[col], b1v = bcs[col + 1];
            float2 v0, v1;
            v0.x = gelu(acc[nt][0] + b0v);
            v0.y = gelu(acc[nt][1] + b1v);
            v1.x = gelu(acc[nt][2] + b0v);
            v1.y = gelu(acc[nt][3] + b1v);
            *(float2*)(g_mu + ((size_t)l * NTOK + n0 + r0) * IND + col) = v0;
            *(float2*)(g_mu + ((size_t)l * NTOK + n0 + r0 + 8) * IND + col) = v1;
        }
    }
    // score: combine the two k-half partials
    sred[tid] = sacc;
    __syncthreads();
    if (tid < 128) {
        int n = n0 + tid;
        float a = sred[tid] + sred[tid + 128] + Bscore[l];
        float s = 1.0f / (1.0f + expf(-a));
        g_f[l * NTOK + n] = s * mask[(size_t)n * LL + l];
    }
}

// ---------------------------------------------------------------------------
// K2 (mma.sync 2xTF32, fp32-in-SMEM): per (128-token tile, capsule pair, l):
//   V[n,l,k,o] = mu_in[l] @ Wvote[l,k] + Bvote.  M=128, N=128, K=64.
// grid (8, 8, 32), block 256. Warp: M=32, N=64 (one capsule). ~70 KB SMEM.
// ---------------------------------------------------------------------------
#define AS2 68    // A row stride (64 + 4)
#define BS2 136   // B row stride (128 + 8)
#define K2_DYN ((128 * AS2 + 64 * BS2 + 128) * 4)
__global__ __launch_bounds__(256) void k2h(const float* __restrict__ Wvote,
                                           const float* __restrict__ Bvote) {
    extern __shared__ __align__(16) float s2[];
    float* As = s2;                      // [128][AS2] fp32
    float* Bs = As + 128 * AS2;          // [64][BS2]  (row=i, col=kl*64+o) fp32
    float* bias = Bs + 64 * BS2;         // [128]

    const int n0 = blockIdx.x * 128, kg = blockIdx.y, l = blockIdx.z;
    const int tid = threadIdx.x, wid = tid >> 5, lane = tid & 31;
    const int g = lane >> 2, tig = lane & 3;

    {
        int m = tid & 127, half = tid >> 7;
        const float* mp = g_mu + ((size_t)l * NTOK + n0 + m) * IND + half * 32;
#pragma unroll
        for (int j = 0; j < 8; j++)
            *(float4*)(As + m * AS2 + half * 32 + j * 4) = *(const float4*)(mp + j * 4);
    }
    {
        int o = tid & 63, kl = (tid >> 6) & 1, ih = tid >> 7;
        const float* wv = Wvote + ((size_t)(l * NOUT + kg * 2 + kl) * IND) * OUTD + o;
#pragma unroll
        for (int j = 0; j < 32; j++) {
            int i = ih * 32 + j;
            Bs[i * BS2 + kl * 64 + o] = wv[(size_t)i * OUTD];
        }
    }
    if (tid < 128)
        bias[tid] = Bvote[(size_t)(l * NOUT + kg * 2 + (tid >> 6)) * OUTD + (tid & 63)];
    __syncthreads();

    const int mrow0 = (wid & 3) * 32, nhalf = wid >> 2;
    float acc[2][8][4] = {};
#pragma unroll
    for (int ks = 0; ks < 8; ks++) {
        const int kk = ks * 8;
        uint32_t ah[2][4], al[2][4];
#pragma unroll
        for (int mf = 0; mf < 2; mf++) {
            int r = mrow0 + mf * 16;
            float v0 = As[(r + g) * AS2 + kk + tig];
            float v1 = As[(r + g + 8) * AS2 + kk + tig];
            float v2 = As[(r + g) * AS2 + kk + tig + 4];
            float v3 = As[(r + g + 8) * AS2 + kk + tig + 4];
            float h0 = tf32r(v0), h1 = tf32r(v1), h2 = tf32r(v2), h3 = tf32r(v3);
            ah[mf][0] = __float_as_uint(h0); al[mf][0] = __float_as_uint(tf32r(v0 - h0));
            ah[mf][1] = __float_as_uint(h1); al[mf][1] = __float_as_uint(tf32r(v1 - h1));
            ah[mf][2] = __float_as_uint(h2); al[mf][2] = __float_as_uint(tf32r(v2 - h2));
            ah[mf][3] = __float_as_uint(h3); al[mf][3] = __float_as_uint(tf32r(v3 - h3));
        }
#pragma unroll
        for (int nt = 0; nt < 8; nt++) {
            int n = nhalf * 64 + nt * 8 + g;
            float bv0 = Bs[(kk + tig) * BS2 + n];
            float bv1 = Bs[(kk + tig + 4) * BS2 + n];
            float bh0f = tf32r(bv0), bh1f = tf32r(bv1);
            uint32_t bh0 = __float_as_uint(bh0f), bh1 = __float_as_uint(bh1f);
            uint32_t bl0 = __float_as_uint(tf32r(bv0 - bh0f));
            uint32_t bl1 = __float_as_uint(tf32r(bv1 - bh1f));
#pragma unroll
            for (int mf = 0; mf < 2; mf++) {
                mma8(acc[mf][nt], al[mf][0], al[mf][1], al[mf][2], al[mf][3], bh0, bh1);
                mma8(acc[mf][nt], ah[mf][0], ah[mf][1], ah[mf][2], ah[mf][3], bl0, bl1);
                mma8(acc[mf][nt], ah[mf][0], ah[mf][1], ah[mf][2], ah[mf][3], bh0, bh1);
            }
        }
    }
    const int kc = kg * 2 + nhalf;
#pragma unroll
    for (int mf = 0; mf < 2; mf++) {
        int r0 = mrow0 + mf * 16 + g;
#pragma unroll
        for (int nt = 0; nt < 8; nt++) {
            int col = nt * 8 + 2 * tig;
            float b0v = bias[nhalf * 64 + col], b1v = bias[nhalf * 64 + col + 1];
            float2 v0, v1;
            v0.x = acc[mf][nt][0] + b0v; v0.y = acc[mf][nt][1] + b1v;
            v1.x = acc[mf][nt][2] + b0v; v1.y = acc[mf][nt][3] + b1v;
            *(float2*)(g_V + (((size_t)(n0 + r0) * LL + l) * NOUT + kc) * OUTD + col) = v0;
            *(float2*)(g_V + (((size_t)(n0 + r0 + 8) * LL + l) * NOUT + kc) * OUTD + col) = v1;
        }
    }
}

// ---------------------------------------------------------------------------
// K3: routing. One CTA per token, 512 threads (16 warps), V in SMEM.
// z-pass: thread per (l,k) pair, straight-line FMA, half-warp shfl softmax.
// ---------------------------------------------------------------------------
#define K3_SMEM_FLOATS (32768 + 1024 * 3 + 512 * 2 + 32 * 2 + 16 * 5 + 16)
__global__ __launch_bounds__(512) void k3_route(
    const float* __restrict__ beta_use, const float* __restrict__ beta_ign,
    const int* __restrict__ iters_p, float* __restrict__ out) {
    extern __shared__ __align__(16) float sm[];
    float* Vs   = sm;              // [512 pairs][64]
    float* mu   = Vs + 32768;      // [16][64]
    float* var  = mu + 1024;
    float* iv   = var + 1024;
    float* R    = iv + 1024;       // [32][16]
    float* ws   = R + 512;         // [32][16]
    float* fs   = ws + 512;        // [32]
    float* bus  = fs + 32;
    float* bis  = bus + 32;
    float* lvs  = bis + 16;
    float* lsa  = lvs + 16;
    float* aout = lsa + 16;
    float* sumw = aout + 16;
    float* sfs  = sumw + 16;

    const int n = blockIdx.x;
    const int tid = threadIdx.x;
    const int warp = tid >> 5, lane = tid & 31;

    {
        const float4* Vg4 = (const float4*)(g_V + (size_t)n * (LL * NOUT * OUTD));
        float4* Vs4 = (float4*)Vs;
#pragma unroll
        for (int i = 0; i < 16; i++) Vs4[tid + i * 512] = Vg4[tid + i * 512];
    }
    if (tid < 32) { fs[tid] = g_f[tid * NTOK + n]; bus[tid] = beta_use[tid]; }
    if (tid < 16) bis[tid] = beta_ign[tid];
    R[tid] = 1.0f / (float)NOUT;
    __syncthreads();
    if (warp == 0) {
        float v = wred(fs[lane]);
        if (lane == 0) sfs[0] = v;
    }
    __syncthreads();

    const int ITERS = *iters_p;
    for (int t = 0; t < ITERS; t++) {
        if (t > 0) {
            iv[tid]       = 1.0f / (2.0f * var[tid] + EPSF);
            iv[tid + 512] = 1.0f / (2.0f * var[tid + 512] + EPSF);
            {   // lvs[k] = 0.5*sum_o log(var+eps); warp k (first 16 warps)
                float s = logf(var[(warp << 6) + lane] + EPSF)
                        + logf(var[(warp << 6) + lane + 32] + EPSF);
                s = wred(s);
                if (lane == 0) lvs[warp] = 0.5f * s;
            }
            if (tid < 16) {
                float a = aout[tid];
                lsa[tid] = fminf(a, 0.0f) - log1pf(expf(-fabsf(a)));
            }
            __syncthreads();
            // z + softmax: thread = pair (l = tid>>4, k = tid&15)
            {
                const int k = tid & 15;
                const int pb = tid << 6, kb = k << 6;
                float s = 0.0f;
#pragma unroll 16
                for (int i = 0; i < 64; i++) {
                    int o = (lane + i) & 63;
                    float d = Vs[pb + o] - mu[kb + o];
                    s = fmaf(d * d, iv[kb + o], s);
                }
                float z = lsa[k] - lvs[k] - s;
                // softmax over k within the 16-lane half-warp
                float m = z;
#pragma unroll
                for (int off = 1; off < 16; off <<= 1)
                    m = fmaxf(m, __shfl_xor_sync(0xffffffffu, m, off));
                float e = expf(z - m);
                float ssum = e;
#pragma unroll
                for (int off = 1; off < 16; off <<= 1)
                    ssum += __shfl_xor_sync(0xffffffffu, ssum, off);
                R[tid] = e / ssum;
            }
            __syncthreads();
        }
        {   // per-k sums; k = warp (first 16 warps), l = lane
            int k = warp;
            float w = fs[lane] * R[(lane << 4) + k];
            ws[(lane << 4) + k] = w;
            float wb = bus[lane] * w;
            float wr = wred(w);
            float wbr = wred(wb);
            if (lane == 0) {
                sumw[k] = wr;
                aout[k] = wbr - bis[k] * (sfs[0] - wr);
            }
        }
        __syncthreads();
        // mu/var: warp k; half-warps split l; float4 over o
        {
            const int k = warp;
            const int lh = lane >> 4;
            const int q = lane & 15;
            float4 S1 = {0.f, 0.f, 0.f, 0.f}, S2 = {0.f, 0.f, 0.f, 0.f};
#pragma unroll
            for (int li = 0; li < 16; li++) {
                int lidx = lh * 16 + li;
                float w = ws[(lidx << 4) + k];
                float4 v = *(const float4*)&Vs[(((lidx << 4) + k) << 6) + 4 * q];
                S1.x += w * v.x; S2.x += w * v.x * v.x;
                S1.y += w * v.y; S2.y += w * v.y * v.y;
                S1.z += w * v.z; S2.z += w * v.z * v.z;
                S1.w += w * v.w; S2.w += w * v.w * v.w;
            }
            S1.x += __shfl_xor_sync(0xffffffffu, S1.x, 16);
            S1.y += __shfl_xor_sync(0xffffffffu, S1.y, 16);
            S1.z += __shfl_xor_sync(0xffffffffu, S1.z, 16);
            S1.w += __shfl_xor_sync(0xffffffffu, S1.w, 16);
            S2.x += __shfl_xor_sync(0xffffffffu, S2.x, 16);
            S2.y += __shfl_xor_sync(0xffffffffu, S2.y, 16);
            S2.z += __shfl_xor_sync(0xffffffffu, S2.z, 16);
            S2.w += __shfl_xor_sync(0xffffffffu, S2.w, 16);
            if (lh == 0) {
                float invd = 1.0f / (sumw[k] + EPSF);
                float4 m4, v4;
                m4.x = S1.x * invd; m4.y = S1.y * invd;
                m4.z = S1.z * invd; m4.w = S1.w * invd;
                v4.x = fmaxf(S2.x * invd - m4.x * m4.x, 0.0f);
                v4.y = fmaxf(S2.y * invd - m4.y * m4.y, 0.0f);
                v4.z = fmaxf(S2.z * invd - m4.z * m4.z, 0.0f);
                v4.w = fmaxf(S2.w * invd - m4.w * m4.w, 0.0f);
                *(float4*)&mu[(k << 6) + 4 * q] = m4;
                *(float4*)&var[(k << 6) + 4 * q] = v4;
            }
        }
        __syncthreads();
    }
    if (tid < 16) out[n * NOUT + tid] = aout[tid];
    float* om = out + NTOK * NOUT + (size_t)n * (NOUT * OUTD);
    om[tid] = mu[tid];
    om[tid + 512] = mu[tid + 512];
}

extern "C" void kernel_launch(void* const* d_in, const int* in_sizes, int n_in,
                              void* d_out, int out_size) {
    const float* x        = (const float*)d_in[0];
    const float* mask     = (const float*)d_in[1];
    const float* Wscore   = (const float*)d_in[2];
    const float* Bscore   = (const float*)d_in[3];
    const float* Wcap     = (const float*)d_in[4];
    const float* Bcap     = (const float*)d_in[5];
    const float* Wvote    = (const float*)d_in[6];
    const float* Bvote    = (const float*)d_in[7];
    const float* beta_use = (const float*)d_in[8];
    const float* beta_ign = (const float*)d_in[9];
    const int*   iters    = (const int*)d_in[10];
    float* out = (float*)d_out;

    const size_t smem3 = (size_t)K3_SMEM_FLOATS * sizeof(float);
    cudaFuncSetAttribute(k2h, cudaFuncAttributeMaxDynamicSharedMemorySize, K2_DYN);
    cudaFuncSetAttribute(k3_route, cudaFuncAttributeMaxDynamicSharedMemorySize, (int)smem3);

    k1h<<<dim3(NTOK / 128, LL), 256>>>(x, mask, Wscore, Bscore, Wcap, Bcap);
    k2h<<<dim3(NTOK / 128, NOUT / 2, LL), 256, K2_DYN>>>(Wvote, Bvote);
    k3_route<<<NTOK, 512, smem3>>>(beta_use, beta_ign, iters, out);
}

// round 9
// speedup vs baseline: 1.5064x; 1.0026x over previous
#include <cuda_runtime.h>
#include <math.h>
#include <stdint.h>

#define NTOK 1024
#define LL   32
#define DD   768
#define IND  64
#define NOUT 16
#define OUTD 64
#define EPSF 1e-8f

__device__ float g_mu[(size_t)LL * NTOK * IND];        // [l][n][i]
__device__ float g_f[LL * NTOK];                       // [l][n]
__device__ float g_V[(size_t)NTOK * LL * NOUT * OUTD]; // [n][l][k][o]

__device__ __forceinline__ float tf32r(float x) {
    uint32_t o;
    asm("cvt.rn.tf32.f32 %0, %1;" : "=r"(o) : "f"(x));
    return __uint_as_float(o);
}
__device__ __forceinline__ void mma8(float c[4], uint32_t a0, uint32_t a1,
                                     uint32_t a2, uint32_t a3,
                                     uint32_t b0, uint32_t b1) {
    asm("mma.sync.aligned.m16n8k8.row.col.f32.tf32.tf32.f32 "
        "{%0,%1,%2,%3}, {%4,%5,%6,%7}, {%8,%9}, {%0,%1,%2,%3};"
        : "+f"(c[0]), "+f"(c[1]), "+f"(c[2]), "+f"(c[3])
        : "r"(a0), "r"(a1), "r"(a2), "r"(a3), "r"(b0), "r"(b1));
}
__device__ __forceinline__ float gelu(float v) {
    return 0.5f * v * (1.0f + erff(v * 0.70710678118654752f));
}
__device__ __forceinline__ float wred(float v) {
#pragma unroll
    for (int o = 16; o; o >>= 1) v += __shfl_xor_sync(0xffffffffu, v, o);
    return v;
}

// ---------------------------------------------------------------------------
// K1 (mma.sync 2xTF32, double-buffered): per (l, 128-token tile).
// Block 256 (8 warps), warp = M16 x N64 tile. 48 K-chunks of 16, 1 sync/chunk.
// ---------------------------------------------------------------------------
#define AS1 20   // As row stride (16 + 4 pad)
#define BS1 72   // Bs row stride (64 + 8 pad)
__global__ __launch_bounds__(256) void k1h(
    const float* __restrict__ x, const float* __restrict__ mask,
    const float* __restrict__ Wscore, const float* __restrict__ Bscore,
    const float* __restrict__ Wcap, const float* __restrict__ Bcap) {
    __shared__ __align__(16) float As[2][128 * AS1];
    __shared__ __align__(16) float Bs[2][16 * BS1];
    __shared__ float Ws[2][16];
    __shared__ float bcs[64];
    __shared__ float sred[256];

    const int l = blockIdx.y, n0 = blockIdx.x * 128;
    const int tid = threadIdx.x, wid = tid >> 5, lane = tid & 31;
    const int g = lane >> 2, tig = lane & 3;
    const int arow = tid & 127, ahalf = tid >> 7;      // A staging: row, k-half
    const int brow = tid >> 4, bcol4 = (tid & 15) * 4; // B staging

    if (tid < 64) bcs[tid] = Bcap[l * IND + tid];

    const float* xl = x + (size_t)(n0 + arow) * (LL * DD) + (size_t)l * DD + ahalf * 8;
    const float* wc = Wcap + (size_t)l * DD * IND;

    // stage chunk 0 into buffer 0
    float4 a_st[2];
    float4 b_st;
    float w_st = 0.0f;
    a_st[0] = *(const float4*)(xl);
    a_st[1] = *(const float4*)(xl + 4);
    b_st = *(const float4*)(wc + (size_t)brow * IND + bcol4);
    if (tid < 16) w_st = Wscore[l * DD + tid];
    *(float4*)(As[0] + arow * AS1 + ahalf * 8) = a_st[0];
    *(float4*)(As[0] + arow * AS1 + ahalf * 8 + 4) = a_st[1];
    *(float4*)(Bs[0] + brow * BS1 + bcol4) = b_st;
    if (tid < 16) Ws[0][tid] = w_st;
    __syncthreads();

    float acc[8][4] = {};
    float sacc = 0.0f;

    for (int c = 0; c < 48; c++) {
        const int buf = c & 1;
        // score partial: a_st still holds chunk c (full fp32)
        {
            int kb = ahalf * 8;
            sacc += a_st[0].x * Ws[buf][kb + 0] + a_st[0].y * Ws[buf][kb + 1]
                  + a_st[0].z * Ws[buf][kb + 2] + a_st[0].w * Ws[buf][kb + 3]
                  + a_st[1].x * Ws[buf][kb + 4] + a_st[1].y * Ws[buf][kb + 5]
                  + a_st[1].z * Ws[buf][kb + 6] + a_st[1].w * Ws[buf][kb + 7];
        }
        // prefetch chunk c+1 into regs
        if (c + 1 < 48) {
            int k0 = (c + 1) * 16;
            a_st[0] = *(const float4*)(xl + k0);
            a_st[1] = *(const float4*)(xl + k0 + 4);
            b_st = *(const float4*)(wc + (size_t)(k0 + brow) * IND + bcol4);
            if (tid < 16) w_st = Wscore[l * DD + k0 + tid];
        }
        // mma on buffer buf: 2 k8 steps, 3 compensated passes, warp tile M16
#pragma unroll
        for (int ks = 0; ks < 2; ks++) {
            const int kk = ks * 8;
            uint32_t ah[4], al[4];
            {
                int r = wid * 16;
                float v0 = As[buf][(r + g) * AS1 + kk + tig];
                float v1 = As[buf][(r + g + 8) * AS1 + kk + tig];
                float v2 = As[buf][(r + g) * AS1 + kk + tig + 4];
                float v3 = As[buf][(r + g + 8) * AS1 + kk + tig + 4];
                float h0 = tf32r(v0), h1 = tf32r(v1), h2 = tf32r(v2), h3 = tf32r(v3);
                ah[0] = __float_as_uint(h0); al[0] = __float_as_uint(tf32r(v0 - h0));
                ah[1] = __float_as_uint(h1); al[1] = __float_as_uint(tf32r(v1 - h1));
                ah[2] = __float_as_uint(h2); al[2] = __float_as_uint(tf32r(v2 - h2));
                ah[3] = __float_as_uint(h3); al[3] = __float_as_uint(tf32r(v3 - h3));
            }
#pragma unroll
            for (int nt = 0; nt < 8; nt++) {
                float bv0 = Bs[buf][(kk + tig) * BS1 + nt * 8 + g];
                float bv1 = Bs[buf][(kk + tig + 4) * BS1 + nt * 8 + g];
                float bh0f = tf32r(bv0), bh1f = tf32r(bv1);
                uint32_t bh0 = __float_as_uint(bh0f), bh1 = __float_as_uint(bh1f);
                uint32_t bl0 = __float_as_uint(tf32r(bv0 - bh0f));
                uint32_t bl1 = __float_as_uint(tf32r(bv1 - bh1f));
                mma8(acc[nt], al[0], al[1], al[2], al[3], bh0, bh1);
                mma8(acc[nt], ah[0], ah[1], ah[2], ah[3], bl0, bl1);
                mma8(acc[nt], ah[0], ah[1], ah[2], ah[3], bh0, bh1);
            }
        }
        // store chunk c+1 into the other buffer (safe: its readers synced at c-1)
        if (c + 1 < 48) {
            const int nb = buf ^ 1;
            *(float4*)(As[nb] + arow * AS1 + ahalf * 8) = a_st[0];
            *(float4*)(As[nb] + arow * AS1 + ahalf * 8 + 4) = a_st[1];
            *(float4*)(Bs[nb] + brow * BS1 + bcol4) = b_st;
            if (tid < 16) Ws[nb][tid] = w_st;
        }
        __syncthreads();
    }
    // epilogue: bias + GELU -> g_mu  (warp rows wid*16+g, +8)
    {
        int r0 = wid * 16 + g;
#pragma unroll
        for (int nt = 0; nt < 8; nt++) {
            int col = nt * 8 + 2 * tig;
            float b0v = bcs[col], b1v = bcs[col + 1];
            float2 v0, v1;
            v0.x = gelu(acc[nt][0] + b0v);
            v0.y = gelu(acc[nt][1] + b1v);
            v1.x = gelu(acc[nt][2] + b0v);
            v1.y = gelu(acc[nt][3] + b1v);
            *(float2*)(g_mu + ((size_t)l * NTOK + n0 + r0) * IND + col) = v0;
            *(float2*)(g_mu + ((size_t)l * NTOK + n0 + r0 + 8) * IND + col) = v1;
        }
    }
    // score: combine the two k-half partials
    sred[tid] = sacc;
    __syncthreads();
    if (tid < 128) {
        int n = n0 + tid;
        float a = sred[tid] + sred[tid + 128] + Bscore[l];
        float s = 1.0f / (1.0f + expf(-a));
        g_f[l * NTOK + n] = s * mask[(size_t)n * LL + l];
    }
}

// ---------------------------------------------------------------------------
// K2 (mma.sync 2xTF32): per (128-token tile, capsule pair, l):
//   V[n,l,k,o] = mu_in[l] @ Wvote[l,k] + Bvote.  M=128, N=128, K=64.
// grid (8, 8, 32), block 256. Warp: M=32, N=64 (one capsule). ~70 KB SMEM.
// Wvote loads float4-coalesced, transposed into SMEM with float4 stores.
// ---------------------------------------------------------------------------
#define AS2 68    // A row stride (64 + 4)
#define BS2 136   // B row stride (128 + 8)
#define K2_DYN ((128 * AS2 + 64 * BS2 + 128) * 4)
__global__ __launch_bounds__(256) void k2h(const float* __restrict__ Wvote,
                                           const float* __restrict__ Bvote) {
    extern __shared__ __align__(16) float s2[];
    float* As = s2;                      // [128][AS2] fp32
    float* Bs = As + 128 * AS2;          // [64][BS2]  (row=i, col=kl*64+o) fp32
    float* bias = Bs + 64 * BS2;         // [128]

    const int n0 = blockIdx.x * 128, kg = blockIdx.y, l = blockIdx.z;
    const int tid = threadIdx.x, wid = tid >> 5, lane = tid & 31;
    const int g = lane >> 2, tig = lane & 3;

    {
        int m = tid & 127, half = tid >> 7;
        const float* mp = g_mu + ((size_t)l * NTOK + n0 + m) * IND + half * 32;
#pragma unroll
        for (int j = 0; j < 8; j++)
            *(float4*)(As + m * AS2 + half * 32 + j * 4) = *(const float4*)(mp + j * 4);
    }
    {   // coalesced Wvote: thread (kl, i0, o4) loads rows i = i0 + 8j
        int kl = tid >> 7, i0 = (tid >> 4) & 7, o4 = (tid & 15) * 4;
        const float* wv = Wvote + (size_t)(l * NOUT + kg * 2 + kl) * IND * OUTD;
#pragma unroll
        for (int j = 0; j < 8; j++) {
            int i = i0 + j * 8;
            float4 v = *(const float4*)(wv + (size_t)i * OUTD + o4);
            *(float4*)(Bs + i * BS2 + kl * 64 + o4) = v;
        }
    }
    if (tid < 128)
        bias[tid] = Bvote[(size_t)(l * NOUT + kg * 2 + (tid >> 6)) * OUTD + (tid & 63)];
    __syncthreads();

    const int mrow0 = (wid & 3) * 32, nhalf = wid >> 2;
    float acc[2][8][4] = {};
#pragma unroll
    for (int ks = 0; ks < 8; ks++) {
        const int kk = ks * 8;
        uint32_t ah[2][4], al[2][4];
#pragma unroll
        for (int mf = 0; mf < 2; mf++) {
            int r = mrow0 + mf * 16;
            float v0 = As[(r + g) * AS2 + kk + tig];
            float v1 = As[(r + g + 8) * AS2 + kk + tig];
            float v2 = As[(r + g) * AS2 + kk + tig + 4];
            float v3 = As[(r + g + 8) * AS2 + kk + tig + 4];
            float h0 = tf32r(v0), h1 = tf32r(v1), h2 = tf32r(v2), h3 = tf32r(v3);
            ah[mf][0] = __float_as_uint(h0); al[mf][0] = __float_as_uint(tf32r(v0 - h0));
            ah[mf][1] = __float_as_uint(h1); al[mf][1] = __float_as_uint(tf32r(v1 - h1));
            ah[mf][2] = __float_as_uint(h2); al[mf][2] = __float_as_uint(tf32r(v2 - h2));
            ah[mf][3] = __float_as_uint(h3); al[mf][3] = __float_as_uint(tf32r(v3 - h3));
        }
#pragma unroll
        for (int nt = 0; nt < 8; nt++) {
            int n = nhalf * 64 + nt * 8 + g;
            float bv0 = Bs[(kk + tig) * BS2 + n];
            float bv1 = Bs[(kk + tig + 4) * BS2 + n];
            float bh0f = tf32r(bv0), bh1f = tf32r(bv1);
            uint32_t bh0 = __float_as_uint(bh0f), bh1 = __float_as_uint(bh1f);
            uint32_t bl0 = __float_as_uint(tf32r(bv0 - bh0f));
            uint32_t bl1 = __float_as_uint(tf32r(bv1 - bh1f));
#pragma unroll
            for (int mf = 0; mf < 2; mf++) {
                mma8(acc[mf][nt], al[mf][0], al[mf][1], al[mf][2], al[mf][3], bh0, bh1);
                mma8(acc[mf][nt], ah[mf][0], ah[mf][1], ah[mf][2], ah[mf][3], bl0, bl1);
                mma8(acc[mf][nt], ah[mf][0], ah[mf][1], ah[mf][2], ah[mf][3], bh0, bh1);
            }
        }
    }
    const int kc = kg * 2 + nhalf;
#pragma unroll
    for (int mf = 0; mf < 2; mf++) {
        int r0 = mrow0 + mf * 16 + g;
#pragma unroll
        for (int nt = 0; nt < 8; nt++) {
            int col = nt * 8 + 2 * tig;
            float b0v = bias[nhalf * 64 + col], b1v = bias[nhalf * 64 + col + 1];
            float2 v0, v1;
            v0.x = acc[mf][nt][0] + b0v; v0.y = acc[mf][nt][1] + b1v;
            v1.x = acc[mf][nt][2] + b0v; v1.y = acc[mf][nt][3] + b1v;
            *(float2*)(g_V + (((size_t)(n0 + r0) * LL + l) * NOUT + kc) * OUTD + col) = v0;
            *(float2*)(g_V + (((size_t)(n0 + r0 + 8) * LL + l) * NOUT + kc) * OUTD + col) = v1;
        }
    }
}

// ---------------------------------------------------------------------------
// K3: routing. One CTA per token, 512 threads (16 warps), V in SMEM.
// z-pass: thread per (l,k) pair, straight-line FMA, half-warp shfl softmax.
// ---------------------------------------------------------------------------
#define K3_SMEM_FLOATS (32768 + 1024 * 3 + 512 * 2 + 32 * 2 + 16 * 5 + 16)
__global__ __launch_bounds__(512) void k3_route(
    const float* __restrict__ beta_use, const float* __restrict__ beta_ign,
    const int* __restrict__ iters_p, float* __restrict__ out) {
    extern __shared__ __align__(16) float sm[];
    float* Vs   = sm;              // [512 pairs][64]
    float* mu   = Vs + 32768;      // [16][64]
    float* var  = mu + 1024;
    float* iv   = var + 1024;
    float* R    = iv + 1024;       // [32][16]
    float* ws   = R + 512;         // [32][16]
    float* fs   = ws + 512;        // [32]
    float* bus  = fs + 32;
    float* bis  = bus + 32;
    float* lvs  = bis + 16;
    float* lsa  = lvs + 16;
    float* aout = lsa + 16;
    float* sumw = aout + 16;
    float* sfs  = sumw + 16;

    const int n = blockIdx.x;
    const int tid = threadIdx.x;
    const int warp = tid >> 5, lane = tid & 31;

    {
        const float4* Vg4 = (const float4*)(g_V + (size_t)n * (LL * NOUT * OUTD));
        float4* Vs4 = (float4*)Vs;
#pragma unroll
        for (int i = 0; i < 16; i++) Vs4[tid + i * 512] = Vg4[tid + i * 512];
    }
    if (tid < 32) { fs[tid] = g_f[tid * NTOK + n]; bus[tid] = beta_use[tid]; }
    if (tid < 16) bis[tid] = beta_ign[tid];
    R[tid] = 1.0f / (float)NOUT;
    __syncthreads();
    if (warp == 0) {
        float v = wred(fs[lane]);
        if (lane == 0) sfs[0] = v;
    }
    __syncthreads();

    const int ITERS = *iters_p;
    for (int t = 0; t < ITERS; t++) {
        if (t > 0) {
            iv[tid]       = 1.0f / (2.0f * var[tid] + EPSF);
            iv[tid + 512] = 1.0f / (2.0f * var[tid + 512] + EPSF);
            {   // lvs[k] = 0.5*sum_o log(var+eps); warp k (first 16 warps)
                float s = logf(var[(warp << 6) + lane] + EPSF)
                        + logf(var[(warp << 6) + lane + 32] + EPSF);
                s = wred(s);
                if (lane == 0) lvs[warp] = 0.5f * s;
            }
            if (tid < 16) {
                float a = aout[tid];
                lsa[tid] = fminf(a, 0.0f) - log1pf(expf(-fabsf(a)));
            }
            __syncthreads();
            // z + softmax: thread = pair (l = tid>>4, k = tid&15)
            {
                const int k = tid & 15;
                const int pb = tid << 6, kb = k << 6;
                float s = 0.0f;
#pragma unroll 16
                for (int i = 0; i < 64; i++) {
                    int o = (lane + i) & 63;
                    float d = Vs[pb + o] - mu[kb + o];
                    s = fmaf(d * d, iv[kb + o], s);
                }
                float z = lsa[k] - lvs[k] - s;
                float m = z;
#pragma unroll
                for (int off = 1; off < 16; off <<= 1)
                    m = fmaxf(m, __shfl_xor_sync(0xffffffffu, m, off));
                float e = expf(z - m);
                float ssum = e;
#pragma unroll
                for (int off = 1; off < 16; off <<= 1)
                    ssum += __shfl_xor_sync(0xffffffffu, ssum, off);
                R[tid] = e / ssum;
            }
            __syncthreads();
        }
        {   // per-k sums; k = warp (first 16 warps), l = lane
            int k = warp;
            float w = fs[lane] * R[(lane << 4) + k];
            ws[(lane << 4) + k] = w;
            float wb = bus[lane] * w;
            float wr = wred(w);
            float wbr = wred(wb);
            if (lane == 0) {
                sumw[k] = wr;
                aout[k] = wbr - bis[k] * (sfs[0] - wr);
            }
        }
        __syncthreads();
        // mu/var: warp k; half-warps split l; float4 over o
        {
            const int k = warp;
            const int lh = lane >> 4;
            const int q = lane & 15;
            float4 S1 = {0.f, 0.f, 0.f, 0.f}, S2 = {0.f, 0.f, 0.f, 0.f};
#pragma unroll
            for (int li = 0; li < 16; li++) {
                int lidx = lh * 16 + li;
                float w = ws[(lidx << 4) + k];
                float4 v = *(const float4*)&Vs[(((lidx << 4) + k) << 6) + 4 * q];
                S1.x += w * v.x; S2.x += w * v.x * v.x;
                S1.y += w * v.y; S2.y += w * v.y * v.y;
                S1.z += w * v.z; S2.z += w * v.z * v.z;
                S1.w += w * v.w; S2.w += w * v.w * v.w;
            }
            S1.x += __shfl_xor_sync(0xffffffffu, S1.x, 16);
            S1.y += __shfl_xor_sync(0xffffffffu, S1.y, 16);
            S1.z += __shfl_xor_sync(0xffffffffu, S1.z, 16);
            S1.w += __shfl_xor_sync(0xffffffffu, S1.w, 16);
            S2.x += __shfl_xor_sync(0xffffffffu, S2.x, 16);
            S2.y += __shfl_xor_sync(0xffffffffu, S2.y, 16);
            S2.z += __shfl_xor_sync(0xffffffffu, S2.z, 16);
            S2.w += __shfl_xor_sync(0xffffffffu, S2.w, 16);
            if (lh == 0) {
                float invd = 1.0f / (sumw[k] + EPSF);
                float4 m4, v4;
                m4.x = S1.x * invd; m4.y = S1.y * invd;
                m4.z = S1.z * invd; m4.w = S1.w * invd;
                v4.x = fmaxf(S2.x * invd - m4.x * m4.x, 0.0f);
                v4.y = fmaxf(S2.y * invd - m4.y * m4.y, 0.0f);
                v4.z = fmaxf(S2.z * invd - m4.z * m4.z, 0.0f);
                v4.w = fmaxf(S2.w * invd - m4.w * m4.w, 0.0f);
                *(float4*)&mu[(k << 6) + 4 * q] = m4;
                *(float4*)&var[(k << 6) + 4 * q] = v4;
            }
        }
        __syncthreads();
    }
    if (tid < 16) out[n * NOUT + tid] = aout[tid];
    float* om = out + NTOK * NOUT + (size_t)n * (NOUT * OUTD);
    om[tid] = mu[tid];
    om[tid + 512] = mu[tid + 512];
}

extern "C" void kernel_launch(void* const* d_in, const int* in_sizes, int n_in,
                              void* d_out, int out_size) {
    const float* x        = (const float*)d_in[0];
    const float* mask     = (const float*)d_in[1];
    const float* Wscore   = (const float*)d_in[2];
    const float* Bscore   = (const float*)d_in[3];
    const float* Wcap     = (const float*)d_in[4];
    const float* Bcap     = (const float*)d_in[5];
    const float* Wvote    = (const float*)d_in[6];
    const float* Bvote    = (const float*)d_in[7];
    const float* beta_use = (const float*)d_in[8];
    const float* beta_ign = (const float*)d_in[9];
    const int*   iters    = (const int*)d_in[10];
    float* out = (float*)d_out;

    const size_t smem3 = (size_t)K3_SMEM_FLOATS * sizeof(float);
    cudaFuncSetAttribute(k2h, cudaFuncAttributeMaxDynamicSharedMemorySize, K2_DYN);
    cudaFuncSetAttribute(k3_route, cudaFuncAttributeMaxDynamicSharedMemorySize, (int)smem3);

    k1h<<<dim3(NTOK / 128, LL), 256>>>(x, mask, Wscore, Bscore, Wcap, Bcap);
    k2h<<<dim3(NTOK / 128, NOUT / 2, LL), 256, K2_DYN>>>(Wvote, Bvote);
    k3_route<<<NTOK, 512, smem3>>>(beta_use, beta_ign, iters, out);
}